// round 4
// baseline (speedup 1.0000x reference)
#include <cuda_runtime.h>

// Problem constants
#define B    64
#define T    512
#define DIN  256
#define H    512
#define G    2048   // 4*H

#define NCTA      128
#define RTHREADS  512

// recurrence v4 SMEM layout (floats)
#define WPAD   516                       // W row stride (512 + 4)
#define HPAD   132                       // h chunk row stride (128 + 4)
#define PPAD   20                        // partial row stride (16 + 4)
#define WS_TOT (32 * WPAD)               // 16512
#define HB_TOT (2 * 32 * HPAD)           // 8448
#define PT_TOT (16 * 32 * PPAD)          // 10240
#define HV_TOT (32 * 12)                 // 384
#define RECUR4_SMEM ((WS_TOT + HB_TOT + PT_TOT + HV_TOT) * 4)

typedef unsigned long long u64;

// ------------------------- device scratch -------------------------
__device__ float g_Wih0[G * DIN];
__device__ float g_Whh0[G * H];
__device__ float g_Wih1[G * H];
__device__ float g_Whh1[G * H];
__device__ float g_bias0[G];
__device__ float g_bias1[G];
__device__ float g_xW[(size_t)T * B * G];     // [t*B+b][G]
__device__ float g_hseq[(size_t)T * B * H];   // [t*B+b][H] (layer0 h output/state)
__device__ float g_h[2][B * H];               // layer1 double-buffered h (g_h[0] = zeros at t=0)
__device__ unsigned int g_bar;

// ------------------------- helpers -------------------------
__device__ __forceinline__ u64 f2pack(float x, float y) {
    u64 r; asm("mov.b64 %0, {%1, %2};" : "=l"(r) : "f"(x), "f"(y)); return r;
}
__device__ __forceinline__ float2 f2unpack(u64 v) {
    float2 r; asm("mov.b64 {%0, %1}, %2;" : "=f"(r.x), "=f"(r.y) : "l"(v)); return r;
}
__device__ __forceinline__ void ffma2(u64& d, u64 a, u64 b) {
    asm("fma.rn.f32x2 %0, %1, %2, %0;" : "+l"(d) : "l"(a), "l"(b));
}
__device__ __forceinline__ float sigmf(float x) {
    return 1.0f / (1.0f + __expf(-x));
}

// ------------------------- prep -------------------------
__global__ void prep_kernel(const float* Wih0, const float* mih0,
                            const float* Whh0, const float* mhh0,
                            const float* bih0, const float* bhh0,
                            const float* Wih1, const float* mih1,
                            const float* Whh1, const float* mhh1,
                            const float* bih1, const float* bhh1)
{
    int idx0 = blockIdx.x * blockDim.x + threadIdx.x;
    int stride = gridDim.x * blockDim.x;
    for (int i = idx0; i < G * DIN; i += stride) g_Wih0[i] = Wih0[i] * mih0[i];
    for (int i = idx0; i < G * H;  i += stride) g_Whh0[i] = Whh0[i] * mhh0[i];
    for (int i = idx0; i < G * H;  i += stride) g_Wih1[i] = Wih1[i] * mih1[i];
    for (int i = idx0; i < G * H;  i += stride) g_Whh1[i] = Whh1[i] * mhh1[i];
    for (int i = idx0; i < G;      i += stride) {
        g_bias0[i] = bih0[i] + bhh0[i];
        g_bias1[i] = bih1[i] + bhh1[i];
    }
}

__global__ void reset_state() {
    int i = blockIdx.x * blockDim.x + threadIdx.x;
    if (i < B * H) { g_h[0][i] = 0.0f; g_h[1][i] = 0.0f; }
    if (i == 0) g_bar = 0u;
}

// ------------------------- projection GEMM (unchanged) -------------------------
__global__ void __launch_bounds__(256, 2) gemm_proj(const float* __restrict__ Aext, int layer)
{
    __shared__ float As[16][132];
    __shared__ float Bs[16][132];

    const float* A    = layer ? g_hseq  : Aext;
    const float* W    = layer ? g_Wih1  : g_Wih0;
    const float* bias = layer ? g_bias1 : g_bias0;
    float*       C    = g_xW;
    const int K       = layer ? H : DIN;
    const int xmode   = layer ? 0 : 1;

    const int tid = threadIdx.x;
    const int ms0 = blockIdx.y << 7;
    const int ns0 = blockIdx.x << 7;
    const int tx  = tid & 15;
    const int ty  = tid >> 4;

    u64 acc[8][4];
#pragma unroll
    for (int i = 0; i < 8; i++)
#pragma unroll
        for (int j = 0; j < 4; j++) acc[i][j] = 0ULL;

    int srow[2], skq[2];
    const float* aptr[2];
    const float* bptr[2];
#pragma unroll
    for (int l = 0; l < 2; l++) {
        int q = tid * 2 + l;
        srow[l] = q >> 2;
        skq[l]  = (q & 3) * 4;
        int m = ms0 + srow[l];
        const float* abase = xmode ? (A + (size_t)((m & (B - 1)) * T + (m >> 6)) * K)
                                   : (A + (size_t)m * K);
        aptr[l] = abase + skq[l];
        bptr[l] = W + (size_t)(ns0 + srow[l]) * K + skq[l];
    }

    for (int kc = 0; kc < K; kc += 16) {
        __syncthreads();
#pragma unroll
        for (int l = 0; l < 2; l++) {
            float4 av = *(const float4*)(aptr[l] + kc);
            As[skq[l] + 0][srow[l]] = av.x;
            As[skq[l] + 1][srow[l]] = av.y;
            As[skq[l] + 2][srow[l]] = av.z;
            As[skq[l] + 3][srow[l]] = av.w;
            float4 bv = *(const float4*)(bptr[l] + kc);
            Bs[skq[l] + 0][srow[l]] = bv.x;
            Bs[skq[l] + 1][srow[l]] = bv.y;
            Bs[skq[l] + 2][srow[l]] = bv.z;
            Bs[skq[l] + 3][srow[l]] = bv.w;
        }
        __syncthreads();
#pragma unroll
        for (int k = 0; k < 16; k++) {
            float4 a0 = *(const float4*)&As[k][ty * 8];
            float4 a1 = *(const float4*)&As[k][ty * 8 + 4];
            u64 b0 = *(const u64*)&Bs[k][tx * 8 + 0];
            u64 b1 = *(const u64*)&Bs[k][tx * 8 + 2];
            u64 b2 = *(const u64*)&Bs[k][tx * 8 + 4];
            u64 b3 = *(const u64*)&Bs[k][tx * 8 + 6];
            float a[8] = {a0.x, a0.y, a0.z, a0.w, a1.x, a1.y, a1.z, a1.w};
#pragma unroll
            for (int i = 0; i < 8; i++) {
                u64 av = f2pack(a[i], a[i]);
                ffma2(acc[i][0], av, b0);
                ffma2(acc[i][1], av, b1);
                ffma2(acc[i][2], av, b2);
                ffma2(acc[i][3], av, b3);
            }
        }
    }

    float bv[8];
#pragma unroll
    for (int j = 0; j < 8; j++) bv[j] = bias[ns0 + tx * 8 + j];
#pragma unroll
    for (int i = 0; i < 8; i++) {
        int m = ms0 + ty * 8 + i;
        float2 p0 = f2unpack(acc[i][0]);
        float2 p1 = f2unpack(acc[i][1]);
        float2 p2 = f2unpack(acc[i][2]);
        float2 p3 = f2unpack(acc[i][3]);
        float4 o0 = make_float4(p0.x + bv[0], p0.y + bv[1], p1.x + bv[2], p1.y + bv[3]);
        float4 o1 = make_float4(p2.x + bv[4], p2.y + bv[5], p3.x + bv[6], p3.y + bv[7]);
        *(float4*)&C[(size_t)m * G + ns0 + tx * 8]     = o0;
        *(float4*)&C[(size_t)m * G + ns0 + tx * 8 + 4] = o1;
    }
}

// ------------------------- recurrence v4 -------------------------
// CTA = 8 units x 32 batches, 512 threads / 16 warps.
// warp = (unit-group ug in {0,1}) x (k-eighth ke in 0..7); lane = batch.
// W broadcast from SMEM; 16 private f32x2 accs per lane; 8-way cross-warp
// SMEM reduction per step; c-state resident in activation threads.
__global__ void __launch_bounds__(RTHREADS, 1) recur_kernel(float* outArg, int layer)
{
    extern __shared__ float sm[];
    float* Ws   = sm;                                // [32 rows][WPAD]
    float* hb   = Ws + WS_TOT;                       // [2][32 b][HPAD]
    float* part = hb + HB_TOT;                       // [16 w][32 b][PPAD]
    float* hvb  = part + PT_TOT;                     // [32 b][12]

    const float* Whh = layer ? g_Whh1 : g_Whh0;
    const int tid = threadIdx.x;
    const int w   = tid >> 5;
    const int ln  = tid & 31;
    const int ug  = w >> 3;          // unit group 0/1 (units ug*4..ug*4+3)
    const int ke  = w & 7;           // k-eighth phase
    const int uTile = blockIdx.x >> 1;
    const int bh    = blockIdx.x & 1;
    const int unit0 = uTile * 8;
    const int bb0   = bh * 32;

    // ---- stage masked W_hh rows into SMEM (row r = u_local*4 + gate) ----
    for (int i = tid; i < 32 * 128; i += RTHREADS) {
        int r   = i >> 7;          // 0..31
        int kc4 = i & 127;
        int u   = r >> 2, g = r & 3;
        float4 v = __ldg((const float4*)(Whh + (size_t)(g * H + unit0 + u) * H + kc4 * 4));
        *(float4*)&Ws[r * WPAD + kc4 * 4] = v;
    }
    __syncthreads();

    const float* Wwarp = Ws + ug * 16 * WPAD;        // this warp's 16 rows
    float* hrow0 = hb + ln * HPAD;
    float* hrow1 = hb + 32 * HPAD + ln * HPAD;

    // staging roles: thread -> (batch, 2 x float4 within 128-float chunk)
    const int sb = tid >> 4;            // 0..31 batch
    const int sq = (tid & 15) * 4;      // first float offset (second at +64)

    // activation roles (threads 0..255)
    const int ul = tid >> 5;            // unit 0..7 (only valid tid<256)
    const int ab = tid & 31;            // batch 0..31
    float creg = 0.0f;

    float* outp = layer ? outArg : (float*)0;

    for (int t = 0; t < T; t++) {
        const float* hin;
        if (layer == 0) hin = (t == 0) ? g_h[0] : (g_hseq + (size_t)(t - 1) * B * H);
        else            hin = g_h[t & 1];
        float* hout = layer ? g_h[(t + 1) & 1] : (g_hseq + (size_t)t * B * H);
        const float* xwt = g_xW + (size_t)t * B * G;

        // prefetch xW gates for activation phase (threads < 256)
        float xg0 = 0.f, xg1 = 0.f, xg2 = 0.f, xg3 = 0.f;
        if (tid < 256) {
            xg0 = __ldg(&xwt[(bb0 + ab) * G + 0 * H + unit0 + ul]);
            xg1 = __ldg(&xwt[(bb0 + ab) * G + 1 * H + unit0 + ul]);
            xg2 = __ldg(&xwt[(bb0 + ab) * G + 2 * H + unit0 + ul]);
            xg3 = __ldg(&xwt[(bb0 + ab) * G + 3 * H + unit0 + ul]);
        }

        u64 acc[4][4];
#pragma unroll
        for (int u = 0; u < 4; u++)
#pragma unroll
            for (int g = 0; g < 4; g++) acc[u][g] = 0ULL;

        // stage chunk 0 (2 float4 per thread)
        float4 s0 = __ldcg((const float4*)(hin + (size_t)(bb0 + sb) * H + sq));
        float4 s1 = __ldcg((const float4*)(hin + (size_t)(bb0 + sb) * H + sq + 64));
        *(float4*)&hb[sb * HPAD + sq]      = s0;
        *(float4*)&hb[sb * HPAD + sq + 64] = s1;
        __syncthreads();

        for (int c = 0; c < 4; c++) {
            if (c < 3) {
                const float* src = hin + (c + 1) * 128;
                s0 = __ldcg((const float4*)(src + (size_t)(bb0 + sb) * H + sq));
                s1 = __ldcg((const float4*)(src + (size_t)(bb0 + sb) * H + sq + 64));
            }
            // compute chunk c: 4 interleaved k4 blocks for this warp
            const float* hc = ((c & 1) ? hrow1 : hrow0);
            const float* wc = Wwarp + c * 128;
#pragma unroll
            for (int i = 0; i < 4; i++) {
                int off = (ke + 8 * i) * 4;
                ulonglong2 hp = *(const ulonglong2*)(hc + off);
                const float* wk = wc + off;
#pragma unroll
                for (int u = 0; u < 4; u++) {
#pragma unroll
                    for (int g = 0; g < 4; g++) {
                        ulonglong2 wp = *(const ulonglong2*)(wk + (u * 4 + g) * WPAD);
                        ffma2(acc[u][g], wp.x, hp.x);
                        ffma2(acc[u][g], wp.y, hp.y);
                    }
                }
            }
            if (c < 3) {
                float* dst = hb + ((c + 1) & 1) * 32 * HPAD;
                *(float4*)&dst[sb * HPAD + sq]      = s0;
                *(float4*)&dst[sb * HPAD + sq + 64] = s1;
                __syncthreads();
            }
        }

        // ---- per-lane horizontal sums -> partials ----
        float* pp = part + (w * 32 + ln) * PPAD;
#pragma unroll
        for (int u = 0; u < 4; u++) {
            float2 q0 = f2unpack(acc[u][0]);
            float2 q1 = f2unpack(acc[u][1]);
            float2 q2 = f2unpack(acc[u][2]);
            float2 q3 = f2unpack(acc[u][3]);
            *(float4*)(pp + u * 4) = make_float4(q0.x + q0.y, q1.x + q1.y,
                                                 q2.x + q2.y, q3.x + q3.y);
        }
        __syncthreads();

        // ---- activation: thread = (unit ul, batch ab), tid < 256 ----
        if (tid < 256) {
            int wb = (ul >> 2) * 8;       // warp group base for this unit
            int us = (ul & 3) * 4;
            float gi = xg0, gf = xg1, gg = xg2, go = xg3;
#pragma unroll
            for (int k = 0; k < 8; k += 2) {
                float4 v0 = *(const float4*)(part + ((wb + k)     * 32 + ab) * PPAD + us);
                float4 v1 = *(const float4*)(part + ((wb + k + 1) * 32 + ab) * PPAD + us);
                gi += v0.x + v1.x; gf += v0.y + v1.y;
                gg += v0.z + v1.z; go += v0.w + v1.w;
            }
            creg = sigmf(gf) * creg + sigmf(gi) * __tanhf(gg);
            float hv = sigmf(go) * __tanhf(creg);
            hvb[ab * 12 + ul] = hv;
        }
        __syncthreads();

        // ---- write h (float4) ----
        if (tid < 64) {
            int b  = tid >> 1;
            int hf = tid & 1;
            float4 v = *(const float4*)&hvb[b * 12 + hf * 4];
            __stcg((float4*)(hout + (size_t)(bb0 + b) * H + unit0 + hf * 4), v);
            if (outp && t == T - 1)
                __stcg((float4*)(outp + (size_t)(bb0 + b) * H + unit0 + hf * 4), v);
        }

        // ---- grid barrier ----
        if (t + 1 < T) {
            __syncthreads();
            if (tid == 0) {
                unsigned int one = 1u;
                asm volatile("red.release.gpu.global.add.u32 [%0], %1;"
                             :: "l"(&g_bar), "r"(one) : "memory");
                unsigned int want = (unsigned int)(t + 1) * (unsigned int)NCTA;
                unsigned int v;
                do {
                    asm volatile("ld.acquire.gpu.global.u32 %0, [%1];"
                                 : "=r"(v) : "l"(&g_bar));
                } while (v < want);
            }
            __syncthreads();
        }
    }
}

// ------------------------- launch -------------------------
extern "C" void kernel_launch(void* const* d_in, const int* in_sizes, int n_in,
                              void* d_out, int out_size)
{
    (void)in_sizes; (void)n_in; (void)out_size;
    const float* x = (const float*)d_in[0];

    cudaFuncSetAttribute(recur_kernel, cudaFuncAttributeMaxDynamicSharedMemorySize, RECUR4_SMEM);

    prep_kernel<<<512, 256>>>(
        (const float*)d_in[1],  (const float*)d_in[5],
        (const float*)d_in[2],  (const float*)d_in[6],
        (const float*)d_in[3],  (const float*)d_in[4],
        (const float*)d_in[7],  (const float*)d_in[11],
        (const float*)d_in[8],  (const float*)d_in[12],
        (const float*)d_in[9],  (const float*)d_in[10]);

    dim3 pgrid(G / 128, (T * B) / 128);

    // layer 0
    gemm_proj<<<pgrid, 256>>>(x, 0);
    reset_state<<<(B * H + 255) / 256, 256>>>();
    recur_kernel<<<NCTA, RTHREADS, RECUR4_SMEM>>>((float*)0, 0);

    // layer 1
    gemm_proj<<<pgrid, 256>>>((const float*)0, 1);
    reset_state<<<(B * H + 255) / 256, 256>>>();
    recur_kernel<<<NCTA, RTHREADS, RECUR4_SMEM>>>((float*)d_out, 1);
}

// round 5
// speedup vs baseline: 1.0398x; 1.0398x over previous
#include <cuda_runtime.h>

// Problem constants
#define B    64
#define T    512
#define DIN  256
#define H    512
#define G    2048   // 4*H

#define NCTA      128
#define RTHREADS  512

// recurrence v5 SMEM layout (floats)
#define WPAD   516                        // W row stride (512+4)
#define HPAD   132                        // h row stride (128+4)
#define BPADP  33                         // partial batch stride
#define WS_TOT (32 * WPAD)                // 16512
#define HB_TOT (2 * 32 * HPAD)            // 8448
#define PT_TOT (4 * 32 * BPADP)           // 4224
#define HV_TOT (32 * 12)                  // 384
#define RECUR5_SMEM ((WS_TOT + HB_TOT + PT_TOT + HV_TOT) * 4)

typedef unsigned long long u64;

// ------------------------- device scratch -------------------------
__device__ float g_Wih0[G * DIN];
__device__ float g_Whh0[G * H];
__device__ float g_Wih1[G * H];
__device__ float g_Whh1[G * H];
__device__ float g_bias0[G];
__device__ float g_bias1[G];
__device__ float g_xW[(size_t)T * B * G];     // [t*B+b][G]
__device__ float g_hseq[(size_t)T * B * H];   // layer0 h sequence (doubles as its state)
__device__ float g_h[2][B * H];               // layer1 double-buffered h (g_h[0]=zeros at t=0)
__device__ unsigned int g_bar;

// ------------------------- helpers -------------------------
__device__ __forceinline__ u64 f2pack(float x, float y) {
    u64 r; asm("mov.b64 %0, {%1, %2};" : "=l"(r) : "f"(x), "f"(y)); return r;
}
__device__ __forceinline__ float2 f2unpack(u64 v) {
    float2 r; asm("mov.b64 {%0, %1}, %2;" : "=f"(r.x), "=f"(r.y) : "l"(v)); return r;
}
__device__ __forceinline__ void ffma2(u64& d, u64 a, u64 b) {
    asm("fma.rn.f32x2 %0, %1, %2, %0;" : "+l"(d) : "l"(a), "l"(b));
}
__device__ __forceinline__ float sigmf(float x) {
    return 1.0f / (1.0f + __expf(-x));
}

// ------------------------- prep -------------------------
__global__ void prep_kernel(const float* Wih0, const float* mih0,
                            const float* Whh0, const float* mhh0,
                            const float* bih0, const float* bhh0,
                            const float* Wih1, const float* mih1,
                            const float* Whh1, const float* mhh1,
                            const float* bih1, const float* bhh1)
{
    int idx0 = blockIdx.x * blockDim.x + threadIdx.x;
    int stride = gridDim.x * blockDim.x;
    for (int i = idx0; i < G * DIN; i += stride) g_Wih0[i] = Wih0[i] * mih0[i];
    for (int i = idx0; i < G * H;  i += stride) g_Whh0[i] = Whh0[i] * mhh0[i];
    for (int i = idx0; i < G * H;  i += stride) g_Wih1[i] = Wih1[i] * mih1[i];
    for (int i = idx0; i < G * H;  i += stride) g_Whh1[i] = Whh1[i] * mhh1[i];
    for (int i = idx0; i < G;      i += stride) {
        g_bias0[i] = bih0[i] + bhh0[i];
        g_bias1[i] = bih1[i] + bhh1[i];
    }
}

__global__ void reset_state() {
    int i = blockIdx.x * blockDim.x + threadIdx.x;
    if (i < B * H) { g_h[0][i] = 0.0f; g_h[1][i] = 0.0f; }
    if (i == 0) g_bar = 0u;
}

// ------------------------- projection GEMM (unchanged) -------------------------
__global__ void __launch_bounds__(256, 2) gemm_proj(const float* __restrict__ Aext, int layer)
{
    __shared__ float As[16][132];
    __shared__ float Bs[16][132];

    const float* A    = layer ? g_hseq  : Aext;
    const float* W    = layer ? g_Wih1  : g_Wih0;
    const float* bias = layer ? g_bias1 : g_bias0;
    float*       C    = g_xW;
    const int K       = layer ? H : DIN;
    const int xmode   = layer ? 0 : 1;

    const int tid = threadIdx.x;
    const int ms0 = blockIdx.y << 7;
    const int ns0 = blockIdx.x << 7;
    const int tx  = tid & 15;
    const int ty  = tid >> 4;

    u64 acc[8][4];
#pragma unroll
    for (int i = 0; i < 8; i++)
#pragma unroll
        for (int j = 0; j < 4; j++) acc[i][j] = 0ULL;

    int srow[2], skq[2];
    const float* aptr[2];
    const float* bptr[2];
#pragma unroll
    for (int l = 0; l < 2; l++) {
        int q = tid * 2 + l;
        srow[l] = q >> 2;
        skq[l]  = (q & 3) * 4;
        int m = ms0 + srow[l];
        const float* abase = xmode ? (A + (size_t)((m & (B - 1)) * T + (m >> 6)) * K)
                                   : (A + (size_t)m * K);
        aptr[l] = abase + skq[l];
        bptr[l] = W + (size_t)(ns0 + srow[l]) * K + skq[l];
    }

    for (int kc = 0; kc < K; kc += 16) {
        __syncthreads();
#pragma unroll
        for (int l = 0; l < 2; l++) {
            float4 av = *(const float4*)(aptr[l] + kc);
            As[skq[l] + 0][srow[l]] = av.x;
            As[skq[l] + 1][srow[l]] = av.y;
            As[skq[l] + 2][srow[l]] = av.z;
            As[skq[l] + 3][srow[l]] = av.w;
            float4 bv = *(const float4*)(bptr[l] + kc);
            Bs[skq[l] + 0][srow[l]] = bv.x;
            Bs[skq[l] + 1][srow[l]] = bv.y;
            Bs[skq[l] + 2][srow[l]] = bv.z;
            Bs[skq[l] + 3][srow[l]] = bv.w;
        }
        __syncthreads();
#pragma unroll
        for (int k = 0; k < 16; k++) {
            float4 a0 = *(const float4*)&As[k][ty * 8];
            float4 a1 = *(const float4*)&As[k][ty * 8 + 4];
            u64 b0 = *(const u64*)&Bs[k][tx * 8 + 0];
            u64 b1 = *(const u64*)&Bs[k][tx * 8 + 2];
            u64 b2 = *(const u64*)&Bs[k][tx * 8 + 4];
            u64 b3 = *(const u64*)&Bs[k][tx * 8 + 6];
            float a[8] = {a0.x, a0.y, a0.z, a0.w, a1.x, a1.y, a1.z, a1.w};
#pragma unroll
            for (int i = 0; i < 8; i++) {
                u64 av = f2pack(a[i], a[i]);
                ffma2(acc[i][0], av, b0);
                ffma2(acc[i][1], av, b1);
                ffma2(acc[i][2], av, b2);
                ffma2(acc[i][3], av, b3);
            }
        }
    }

    float bv[8];
#pragma unroll
    for (int j = 0; j < 8; j++) bv[j] = bias[ns0 + tx * 8 + j];
#pragma unroll
    for (int i = 0; i < 8; i++) {
        int m = ms0 + ty * 8 + i;
        float2 p0 = f2unpack(acc[i][0]);
        float2 p1 = f2unpack(acc[i][1]);
        float2 p2 = f2unpack(acc[i][2]);
        float2 p3 = f2unpack(acc[i][3]);
        float4 o0 = make_float4(p0.x + bv[0], p0.y + bv[1], p1.x + bv[2], p1.y + bv[3]);
        float4 o1 = make_float4(p2.x + bv[4], p2.y + bv[5], p3.x + bv[6], p3.y + bv[7]);
        *(float4*)&C[(size_t)m * G + ns0 + tx * 8]     = o0;
        *(float4*)&C[(size_t)m * G + ns0 + tx * 8 + 4] = o1;
    }
}

// ------------------------- recurrence v5 -------------------------
// CTA = 8 units x 32 batches (128 CTAs), 512 threads.
// warp = (rowgroup rg 0..3 : 8 gate-rows) x (k-quarter kq 0..3)
// lane = (ks 0..3 : 8-k sub-slice) x (bq 0..7 : batches bq+8i, i=0..3)
// Each lane: 8 rows x 4 batches f32x2 accumulators; per k4: 8 W-LDS + 4 h-LDS
// -> 64 FFMA2 (5.3 FFMA2/LDS). ks reduced via 2 shuffles, kq via SMEM.
__global__ void __launch_bounds__(RTHREADS, 1) recur_kernel(float* outArg, int layer)
{
    extern __shared__ float sm[];
    float* Ws   = sm;                                // [32 rows][WPAD]
    float* hb   = Ws + WS_TOT;                       // [2][32 b][HPAD]
    float* part = hb + HB_TOT;                       // [4 kq][32 row][BPADP]
    float* hvb  = part + PT_TOT;                     // [32 b][12]

    const float* Whh = layer ? g_Whh1 : g_Whh0;
    const int tid = threadIdx.x;
    const int w   = tid >> 5;
    const int ln  = tid & 31;
    const int rg  = w >> 2;          // rowgroup: rows rg*8 .. rg*8+7
    const int kq  = w & 3;           // k-quarter
    const int ks  = ln >> 3;         // k-sub (8 k)
    const int bq  = ln & 7;          // batch quad: batches bq+8i
    const int uTile = blockIdx.x >> 1;
    const int bh    = blockIdx.x & 1;
    const int unit0 = uTile * 8;
    const int bb0   = bh * 32;

    // ---- stage masked W_hh rows into SMEM (CTA row r = u*4 + g) ----
    for (int i = tid; i < 32 * 128; i += RTHREADS) {
        int r   = i >> 7;          // 0..31
        int kc4 = i & 127;
        int u   = r >> 2, g = r & 3;
        float4 v = __ldg((const float4*)(Whh + (size_t)(g * H + unit0 + u) * H + kc4 * 4));
        *(float4*)&Ws[r * WPAD + kc4 * 4] = v;
    }
    __syncthreads();

    const float* Wwarp = Ws + rg * 8 * WPAD;
    const int klocal = kq * 32 + ks * 8;     // lane k base within a 128-chunk

    // staging roles: thread -> (batch sb, float4 q); chunk = 32 b x 128 k
    const int sb = tid >> 4;            // 0..31
    const int sq = (tid & 15) * 4;      // 0..60 (second load at +64)

    // activation roles (threads 0..255)
    const int ul = tid >> 5;            // unit 0..7
    const int ab = tid & 31;            // batch 0..31
    float creg = 0.0f;

    float* outp = layer ? outArg : (float*)0;

    for (int t = 0; t < T; t++) {
        const float* hin;
        if (layer == 0) hin = (t == 0) ? g_h[0] : (g_hseq + (size_t)(t - 1) * B * H);
        else            hin = g_h[t & 1];
        float* hout = layer ? g_h[(t + 1) & 1] : (g_hseq + (size_t)t * B * H);
        const float* xwt = g_xW + (size_t)t * B * G;

        // prefetch xW gates for activation phase (threads < 256)
        float xg0 = 0.f, xg1 = 0.f, xg2 = 0.f, xg3 = 0.f;
        if (tid < 256) {
            xg0 = __ldg(&xwt[(bb0 + ab) * G + 0 * H + unit0 + ul]);
            xg1 = __ldg(&xwt[(bb0 + ab) * G + 1 * H + unit0 + ul]);
            xg2 = __ldg(&xwt[(bb0 + ab) * G + 2 * H + unit0 + ul]);
            xg3 = __ldg(&xwt[(bb0 + ab) * G + 3 * H + unit0 + ul]);
        }

        u64 acc[8][4];
#pragma unroll
        for (int j = 0; j < 8; j++)
#pragma unroll
            for (int i = 0; i < 4; i++) acc[j][i] = 0ULL;

        // stage chunk 0
        float4 s0 = __ldcg((const float4*)(hin + (size_t)(bb0 + sb) * H + sq));
        float4 s1 = __ldcg((const float4*)(hin + (size_t)(bb0 + sb) * H + sq + 64));
        *(float4*)&hb[sb * HPAD + sq]      = s0;
        *(float4*)&hb[sb * HPAD + sq + 64] = s1;
        __syncthreads();

        for (int c = 0; c < 4; c++) {
            if (c < 3) {
                const float* src = hin + (c + 1) * 128;
                s0 = __ldcg((const float4*)(src + (size_t)(bb0 + sb) * H + sq));
                s1 = __ldcg((const float4*)(src + (size_t)(bb0 + sb) * H + sq + 64));
            }
            const float* hc = hb + (c & 1) * 32 * HPAD;
            const float* wc = Wwarp + c * 128 + klocal;
#pragma unroll
            for (int k4 = 0; k4 < 2; k4++) {
                // h fragments: 4 batches (bq + 8i), 4 k each
                ulonglong2 hp[4];
#pragma unroll
                for (int i = 0; i < 4; i++)
                    hp[i] = *(const ulonglong2*)(hc + (bq + 8 * i) * HPAD + klocal + k4 * 4);
                // rows in two halves of 4 (keeps W transients at 8 regs)
#pragma unroll
                for (int hhalf = 0; hhalf < 2; hhalf++) {
                    ulonglong2 wp[4];
#pragma unroll
                    for (int j = 0; j < 4; j++)
                        wp[j] = *(const ulonglong2*)(wc + (hhalf * 4 + j) * WPAD + k4 * 4);
#pragma unroll
                    for (int j = 0; j < 4; j++) {
#pragma unroll
                        for (int i = 0; i < 4; i++) {
                            ffma2(acc[hhalf * 4 + j][i], wp[j].x, hp[i].x);
                            ffma2(acc[hhalf * 4 + j][i], wp[j].y, hp[i].y);
                        }
                    }
                }
            }
            if (c < 3) {
                float* dst = hb + ((c + 1) & 1) * 32 * HPAD;
                *(float4*)&dst[sb * HPAD + sq]      = s0;
                *(float4*)&dst[sb * HPAD + sq + 64] = s1;
                __syncthreads();
            }
        }

        // ---- reduce over ks (2 butterfly rounds), then write kq-partials ----
        float v[8][4];
#pragma unroll
        for (int j = 0; j < 8; j++)
#pragma unroll
            for (int i = 0; i < 4; i++) {
                float2 s = f2unpack(acc[j][i]);
                v[j][i] = s.x + s.y;
            }
#pragma unroll
        for (int j = 0; j < 8; j++)
#pragma unroll
            for (int i = 0; i < 4; i++) {
                v[j][i] += __shfl_xor_sync(0xffffffffu, v[j][i], 8);
                v[j][i] += __shfl_xor_sync(0xffffffffu, v[j][i], 16);
            }
        // lane (ks,bq) writes rows rg*8 + ks*2 + {0,1}, batches bq+8i
        {
            float* pb = part + kq * (32 * BPADP);
#pragma unroll
            for (int jj = 0; jj < 2; jj++) {
                int j = ks * 2 + jj;
                float* pr = pb + (rg * 8 + j) * BPADP;
#pragma unroll
                for (int i = 0; i < 4; i++)
                    pr[bq + 8 * i] = v[j][i];
            }
        }
        __syncthreads();

        // ---- activation: thread = (unit ul, batch ab), tid < 256 ----
        if (tid < 256) {
            float gate[4];
#pragma unroll
            for (int g = 0; g < 4; g++) {
                int r = ul * 4 + g;
                gate[g] = part[0 * 32 * BPADP + r * BPADP + ab]
                        + part[1 * 32 * BPADP + r * BPADP + ab]
                        + part[2 * 32 * BPADP + r * BPADP + ab]
                        + part[3 * 32 * BPADP + r * BPADP + ab];
            }
            float gi = gate[0] + xg0, gf = gate[1] + xg1;
            float gg = gate[2] + xg2, go = gate[3] + xg3;
            creg = sigmf(gf) * creg + sigmf(gi) * __tanhf(gg);
            float hv = sigmf(go) * __tanhf(creg);
            hvb[ab * 12 + ul] = hv;
        }
        __syncthreads();

        // ---- write h + release fence by writers ----
        if (tid < 64) {
            int b  = tid >> 1;
            int hf = tid & 1;
            float4 vv = *(const float4*)&hvb[b * 12 + hf * 4];
            __stcg((float4*)(hout + (size_t)(bb0 + b) * H + unit0 + hf * 4), vv);
            if (outp && t == T - 1)
                __stcg((float4*)(outp + (size_t)(bb0 + b) * H + unit0 + hf * 4), vv);
            asm volatile("fence.acq_rel.gpu;" ::: "memory");
        }

        // ---- grid barrier ----
        if (t + 1 < T) {
            __syncthreads();
            if (tid == 0) {
                unsigned int one = 1u;
                asm volatile("red.release.gpu.global.add.u32 [%0], %1;"
                             :: "l"(&g_bar), "r"(one) : "memory");
                unsigned int want = (unsigned int)(t + 1) * (unsigned int)NCTA;
                unsigned int vv;
                do {
                    asm volatile("ld.acquire.gpu.global.u32 %0, [%1];"
                                 : "=r"(vv) : "l"(&g_bar));
                } while (vv < want);
            }
            __syncthreads();
        }
    }
}

// ------------------------- launch -------------------------
extern "C" void kernel_launch(void* const* d_in, const int* in_sizes, int n_in,
                              void* d_out, int out_size)
{
    (void)in_sizes; (void)n_in; (void)out_size;
    const float* x = (const float*)d_in[0];

    cudaFuncSetAttribute(recur_kernel, cudaFuncAttributeMaxDynamicSharedMemorySize, RECUR5_SMEM);

    prep_kernel<<<512, 256>>>(
        (const float*)d_in[1],  (const float*)d_in[5],
        (const float*)d_in[2],  (const float*)d_in[6],
        (const float*)d_in[3],  (const float*)d_in[4],
        (const float*)d_in[7],  (const float*)d_in[11],
        (const float*)d_in[8],  (const float*)d_in[12],
        (const float*)d_in[9],  (const float*)d_in[10]);

    dim3 pgrid(G / 128, (T * B) / 128);

    // layer 0
    gemm_proj<<<pgrid, 256>>>(x, 0);
    reset_state<<<(B * H + 255) / 256, 256>>>();
    recur_kernel<<<NCTA, RTHREADS, RECUR5_SMEM>>>((float*)0, 0);

    // layer 1
    gemm_proj<<<pgrid, 256>>>((const float*)0, 1);
    reset_state<<<(B * H + 255) / 256, 256>>>();
    recur_kernel<<<NCTA, RTHREADS, RECUR5_SMEM>>>((float*)d_out, 1);
}

// round 6
// speedup vs baseline: 1.1551x; 1.1109x over previous
#include <cuda_runtime.h>

// Problem constants
#define B    64
#define T    512
#define DIN  256
#define H    512
#define G    2048   // 4*H

#define NCTA      128
#define RTHREADS  512

// recurrence v6 SMEM layout (floats)
#define WPAD   516                        // W row stride (512+4)
#define HSTR   516                        // full-h row stride (512+4)
#define BPADP  33                         // partial batch stride
#define WS_TOT (32 * WPAD)                // 16512
#define HF_TOT (32 * HSTR)                // 16512
#define PT_TOT (4 * 32 * BPADP)           // 4224
#define HV_TOT (32 * 12)                  // 384
#define RECUR6_SMEM ((WS_TOT + HF_TOT + PT_TOT + HV_TOT) * 4)

typedef unsigned long long u64;

// ------------------------- device scratch -------------------------
__device__ float g_Wih0[G * DIN];
__device__ float g_Whh0[G * H];
__device__ float g_Wih1[G * H];
__device__ float g_Whh1[G * H];
__device__ float g_bias0[G];
__device__ float g_bias1[G];
__device__ float g_xW[(size_t)T * B * G];     // [t*B+b][G]
__device__ float g_hseq[(size_t)T * B * H];   // layer0 h sequence (doubles as its state)
__device__ float g_h[2][B * H];               // layer1 double-buffered h (g_h[0]=zeros at t=0)
__device__ unsigned int g_bar2[2][16];        // per-batch-half barrier counters (padded line)

// ------------------------- helpers -------------------------
__device__ __forceinline__ u64 f2pack(float x, float y) {
    u64 r; asm("mov.b64 %0, {%1, %2};" : "=l"(r) : "f"(x), "f"(y)); return r;
}
__device__ __forceinline__ float2 f2unpack(u64 v) {
    float2 r; asm("mov.b64 {%0, %1}, %2;" : "=f"(r.x), "=f"(r.y) : "l"(v)); return r;
}
__device__ __forceinline__ void ffma2(u64& d, u64 a, u64 b) {
    asm("fma.rn.f32x2 %0, %1, %2, %0;" : "+l"(d) : "l"(a), "l"(b));
}
__device__ __forceinline__ float sigmf(float x) {
    return 1.0f / (1.0f + __expf(-x));
}

// ------------------------- prep -------------------------
__global__ void prep_kernel(const float* Wih0, const float* mih0,
                            const float* Whh0, const float* mhh0,
                            const float* bih0, const float* bhh0,
                            const float* Wih1, const float* mih1,
                            const float* Whh1, const float* mhh1,
                            const float* bih1, const float* bhh1)
{
    int idx0 = blockIdx.x * blockDim.x + threadIdx.x;
    int stride = gridDim.x * blockDim.x;
    for (int i = idx0; i < G * DIN; i += stride) g_Wih0[i] = Wih0[i] * mih0[i];
    for (int i = idx0; i < G * H;  i += stride) g_Whh0[i] = Whh0[i] * mhh0[i];
    for (int i = idx0; i < G * H;  i += stride) g_Wih1[i] = Wih1[i] * mih1[i];
    for (int i = idx0; i < G * H;  i += stride) g_Whh1[i] = Whh1[i] * mhh1[i];
    for (int i = idx0; i < G;      i += stride) {
        g_bias0[i] = bih0[i] + bhh0[i];
        g_bias1[i] = bih1[i] + bhh1[i];
    }
}

__global__ void reset_state() {
    int i = blockIdx.x * blockDim.x + threadIdx.x;
    if (i < B * H) { g_h[0][i] = 0.0f; g_h[1][i] = 0.0f; }
    if (i < 32) g_bar2[i >> 4][i & 15] = 0u;
}

// ------------------------- projection GEMM (unchanged) -------------------------
__global__ void __launch_bounds__(256, 2) gemm_proj(const float* __restrict__ Aext, int layer)
{
    __shared__ float As[16][132];
    __shared__ float Bs[16][132];

    const float* A    = layer ? g_hseq  : Aext;
    const float* W    = layer ? g_Wih1  : g_Wih0;
    const float* bias = layer ? g_bias1 : g_bias0;
    float*       C    = g_xW;
    const int K       = layer ? H : DIN;
    const int xmode   = layer ? 0 : 1;

    const int tid = threadIdx.x;
    const int ms0 = blockIdx.y << 7;
    const int ns0 = blockIdx.x << 7;
    const int tx  = tid & 15;
    const int ty  = tid >> 4;

    u64 acc[8][4];
#pragma unroll
    for (int i = 0; i < 8; i++)
#pragma unroll
        for (int j = 0; j < 4; j++) acc[i][j] = 0ULL;

    int srow[2], skq[2];
    const float* aptr[2];
    const float* bptr[2];
#pragma unroll
    for (int l = 0; l < 2; l++) {
        int q = tid * 2 + l;
        srow[l] = q >> 2;
        skq[l]  = (q & 3) * 4;
        int m = ms0 + srow[l];
        const float* abase = xmode ? (A + (size_t)((m & (B - 1)) * T + (m >> 6)) * K)
                                   : (A + (size_t)m * K);
        aptr[l] = abase + skq[l];
        bptr[l] = W + (size_t)(ns0 + srow[l]) * K + skq[l];
    }

    for (int kc = 0; kc < K; kc += 16) {
        __syncthreads();
#pragma unroll
        for (int l = 0; l < 2; l++) {
            float4 av = *(const float4*)(aptr[l] + kc);
            As[skq[l] + 0][srow[l]] = av.x;
            As[skq[l] + 1][srow[l]] = av.y;
            As[skq[l] + 2][srow[l]] = av.z;
            As[skq[l] + 3][srow[l]] = av.w;
            float4 bv = *(const float4*)(bptr[l] + kc);
            Bs[skq[l] + 0][srow[l]] = bv.x;
            Bs[skq[l] + 1][srow[l]] = bv.y;
            Bs[skq[l] + 2][srow[l]] = bv.z;
            Bs[skq[l] + 3][srow[l]] = bv.w;
        }
        __syncthreads();
#pragma unroll
        for (int k = 0; k < 16; k++) {
            float4 a0 = *(const float4*)&As[k][ty * 8];
            float4 a1 = *(const float4*)&As[k][ty * 8 + 4];
            u64 b0 = *(const u64*)&Bs[k][tx * 8 + 0];
            u64 b1 = *(const u64*)&Bs[k][tx * 8 + 2];
            u64 b2 = *(const u64*)&Bs[k][tx * 8 + 4];
            u64 b3 = *(const u64*)&Bs[k][tx * 8 + 6];
            float a[8] = {a0.x, a0.y, a0.z, a0.w, a1.x, a1.y, a1.z, a1.w};
#pragma unroll
            for (int i = 0; i < 8; i++) {
                u64 av = f2pack(a[i], a[i]);
                ffma2(acc[i][0], av, b0);
                ffma2(acc[i][1], av, b1);
                ffma2(acc[i][2], av, b2);
                ffma2(acc[i][3], av, b3);
            }
        }
    }

    float bv[8];
#pragma unroll
    for (int j = 0; j < 8; j++) bv[j] = bias[ns0 + tx * 8 + j];
#pragma unroll
    for (int i = 0; i < 8; i++) {
        int m = ms0 + ty * 8 + i;
        float2 p0 = f2unpack(acc[i][0]);
        float2 p1 = f2unpack(acc[i][1]);
        float2 p2 = f2unpack(acc[i][2]);
        float2 p3 = f2unpack(acc[i][3]);
        float4 o0 = make_float4(p0.x + bv[0], p0.y + bv[1], p1.x + bv[2], p1.y + bv[3]);
        float4 o1 = make_float4(p2.x + bv[4], p2.y + bv[5], p3.x + bv[6], p3.y + bv[7]);
        *(float4*)&C[(size_t)m * G + ns0 + tx * 8]     = o0;
        *(float4*)&C[(size_t)m * G + ns0 + tx * 8 + 4] = o1;
    }
}

// ------------------------- recurrence v6 -------------------------
// CTA = 8 units x 32 batches (128 CTAs), 512 threads.
// Full h tile (32 b x 512) staged in ONE wave -> single sync -> one
// uninterrupted fma burst over all 4 k-chunks. Two independent 64-CTA
// barriers (batch halves never interact).
__global__ void __launch_bounds__(RTHREADS, 1) recur_kernel(float* outArg, int layer)
{
    extern __shared__ float sm[];
    float* Ws    = sm;                               // [32 rows][WPAD]
    float* hfull = Ws + WS_TOT;                      // [32 b][HSTR]
    float* part  = hfull + HF_TOT;                   // [4 kq][32 row][BPADP]
    float* hvb   = part + PT_TOT;                    // [32 b][12]

    const float* Whh = layer ? g_Whh1 : g_Whh0;
    const int tid = threadIdx.x;
    const int w   = tid >> 5;
    const int ln  = tid & 31;
    const int rg  = w >> 2;          // rowgroup: rows rg*8 .. rg*8+7
    const int kq  = w & 3;           // k-quarter
    const int ks  = ln >> 3;         // k-sub (8 k)
    const int bq  = ln & 7;          // batch quad: batches bq+8i
    const int uTile = blockIdx.x >> 1;
    const int bh    = blockIdx.x & 1;
    const int unit0 = uTile * 8;
    const int bb0   = bh * 32;
    unsigned int* barp = &g_bar2[bh][0];

    // ---- stage masked W_hh rows into SMEM (CTA row r = u*4 + g) ----
    for (int i = tid; i < 32 * 128; i += RTHREADS) {
        int r   = i >> 7;
        int kc4 = i & 127;
        int u   = r >> 2, g = r & 3;
        float4 v = __ldg((const float4*)(Whh + (size_t)(g * H + unit0 + u) * H + kc4 * 4));
        *(float4*)&Ws[r * WPAD + kc4 * 4] = v;
    }

    const float* Wwarp = Ws + rg * 8 * WPAD;
    const int klocal = kq * 32 + ks * 8;

    // staging roles: thread -> (batch sb, float4 column q), 8 float4 each
    const int sb = tid >> 4;            // 0..31
    const int sq = (tid & 15) * 4;      // 0..60 (j-th at +64j)

    // activation roles (threads 0..255)
    const int ul = tid >> 5;            // unit 0..7
    const int ab = tid & 31;            // batch 0..31
    float creg = 0.0f;

    float* outp = layer ? outArg : (float*)0;

    for (int t = 0; t < T; t++) {
        const float* hin;
        if (layer == 0) hin = (t == 0) ? g_h[0] : (g_hseq + (size_t)(t - 1) * B * H);
        else            hin = g_h[t & 1];
        float* hout = layer ? g_h[(t + 1) & 1] : (g_hseq + (size_t)t * B * H);
        const float* xwt = g_xW + (size_t)t * B * G;

        // prefetch xW gates (independent of h -> issue first)
        float xg0 = 0.f, xg1 = 0.f, xg2 = 0.f, xg3 = 0.f;
        if (tid < 256) {
            xg0 = __ldg(&xwt[(bb0 + ab) * G + 0 * H + unit0 + ul]);
            xg1 = __ldg(&xwt[(bb0 + ab) * G + 1 * H + unit0 + ul]);
            xg2 = __ldg(&xwt[(bb0 + ab) * G + 2 * H + unit0 + ul]);
            xg3 = __ldg(&xwt[(bb0 + ab) * G + 3 * H + unit0 + ul]);
        }

        // ---- stage full h tile in one wave (8 LDG.128 in flight/thread) ----
        {
            const float* hrow = hin + (size_t)(bb0 + sb) * H + sq;
            float4 hv[8];
#pragma unroll
            for (int j = 0; j < 8; j++)
                hv[j] = __ldcg((const float4*)(hrow + j * 64));
            float* srow = hfull + sb * HSTR + sq;
#pragma unroll
            for (int j = 0; j < 8; j++)
                *(float4*)(srow + j * 64) = hv[j];
        }
        __syncthreads();

        // ---- one uninterrupted fma burst over 4 k-chunks ----
        u64 acc[8][4];
#pragma unroll
        for (int j = 0; j < 8; j++)
#pragma unroll
            for (int i = 0; i < 4; i++) acc[j][i] = 0ULL;

#pragma unroll
        for (int c = 0; c < 4; c++) {
            const float* hc = hfull + c * 128 + klocal;
            const float* wc = Wwarp + c * 128 + klocal;
#pragma unroll
            for (int k4 = 0; k4 < 2; k4++) {
                ulonglong2 hp[4];
#pragma unroll
                for (int i = 0; i < 4; i++)
                    hp[i] = *(const ulonglong2*)(hc + (bq + 8 * i) * HSTR + k4 * 4);
#pragma unroll
                for (int hhalf = 0; hhalf < 2; hhalf++) {
                    ulonglong2 wp[4];
#pragma unroll
                    for (int j = 0; j < 4; j++)
                        wp[j] = *(const ulonglong2*)(wc + (hhalf * 4 + j) * WPAD + k4 * 4);
#pragma unroll
                    for (int j = 0; j < 4; j++) {
#pragma unroll
                        for (int i = 0; i < 4; i++) {
                            ffma2(acc[hhalf * 4 + j][i], wp[j].x, hp[i].x);
                            ffma2(acc[hhalf * 4 + j][i], wp[j].y, hp[i].y);
                        }
                    }
                }
            }
        }

        // ---- reduce over ks (2 butterflies), write kq-partials ----
        float v[8][4];
#pragma unroll
        for (int j = 0; j < 8; j++)
#pragma unroll
            for (int i = 0; i < 4; i++) {
                float2 s = f2unpack(acc[j][i]);
                v[j][i] = s.x + s.y;
            }
#pragma unroll
        for (int j = 0; j < 8; j++)
#pragma unroll
            for (int i = 0; i < 4; i++) {
                v[j][i] += __shfl_xor_sync(0xffffffffu, v[j][i], 8);
                v[j][i] += __shfl_xor_sync(0xffffffffu, v[j][i], 16);
            }
        {
            float* pb = part + kq * (32 * BPADP);
#pragma unroll
            for (int jj = 0; jj < 2; jj++) {
                int j = ks * 2 + jj;
                float* pr = pb + (rg * 8 + j) * BPADP;
#pragma unroll
                for (int i = 0; i < 4; i++)
                    pr[bq + 8 * i] = v[j][i];
            }
        }
        __syncthreads();

        // ---- activation: thread = (unit ul, batch ab), tid < 256 ----
        if (tid < 256) {
            float gate[4];
#pragma unroll
            for (int g = 0; g < 4; g++) {
                int r = ul * 4 + g;
                gate[g] = part[0 * 32 * BPADP + r * BPADP + ab]
                        + part[1 * 32 * BPADP + r * BPADP + ab]
                        + part[2 * 32 * BPADP + r * BPADP + ab]
                        + part[3 * 32 * BPADP + r * BPADP + ab];
            }
            float gi = gate[0] + xg0, gf = gate[1] + xg1;
            float gg = gate[2] + xg2, go = gate[3] + xg3;
            creg = sigmf(gf) * creg + sigmf(gi) * __tanhf(gg);
            float hv = sigmf(go) * __tanhf(creg);
            hvb[ab * 12 + ul] = hv;
        }
        __syncthreads();

        // ---- write h ----
        if (tid < 64) {
            int b  = tid >> 1;
            int hf = tid & 1;
            float4 vv = *(const float4*)&hvb[b * 12 + hf * 4];
            __stcg((float4*)(hout + (size_t)(bb0 + b) * H + unit0 + hf * 4), vv);
            if (outp && t == T - 1)
                __stcg((float4*)(outp + (size_t)(bb0 + b) * H + unit0 + hf * 4), vv);
        }

        // ---- per-half grid barrier (64 CTAs) ----
        if (t + 1 < T) {
            __syncthreads();
            if (tid == 0) {
                unsigned int one = 1u;
                asm volatile("red.release.gpu.global.add.u32 [%0], %1;"
                             :: "l"(barp), "r"(one) : "memory");
                unsigned int want = (unsigned int)(t + 1) * 64u;
                unsigned int vv;
                do {
                    asm volatile("ld.acquire.gpu.global.u32 %0, [%1];"
                                 : "=r"(vv) : "l"(barp));
                } while (vv < want);
            }
            __syncthreads();
        }
    }
}

// ------------------------- launch -------------------------
extern "C" void kernel_launch(void* const* d_in, const int* in_sizes, int n_in,
                              void* d_out, int out_size)
{
    (void)in_sizes; (void)n_in; (void)out_size;
    const float* x = (const float*)d_in[0];

    cudaFuncSetAttribute(recur_kernel, cudaFuncAttributeMaxDynamicSharedMemorySize, RECUR6_SMEM);

    prep_kernel<<<512, 256>>>(
        (const float*)d_in[1],  (const float*)d_in[5],
        (const float*)d_in[2],  (const float*)d_in[6],
        (const float*)d_in[3],  (const float*)d_in[4],
        (const float*)d_in[7],  (const float*)d_in[11],
        (const float*)d_in[8],  (const float*)d_in[12],
        (const float*)d_in[9],  (const float*)d_in[10]);

    dim3 pgrid(G / 128, (T * B) / 128);

    // layer 0
    gemm_proj<<<pgrid, 256>>>(x, 0);
    reset_state<<<(B * H + 255) / 256, 256>>>();
    recur_kernel<<<NCTA, RTHREADS, RECUR6_SMEM>>>((float*)0, 0);

    // layer 1
    gemm_proj<<<pgrid, 256>>>((const float*)0, 1);
    reset_state<<<(B * H + 255) / 256, 256>>>();
    recur_kernel<<<NCTA, RTHREADS, RECUR6_SMEM>>>((float*)d_out, 1);
}

// round 8
// speedup vs baseline: 1.3462x; 1.1655x over previous
#include <cuda_runtime.h>
#include <cuda_bf16.h>
#include <cstdint>

// Problem constants
#define B    64
#define T    512
#define DIN  256
#define H    512
#define G    2048   // 4*H

#define NCTA      128
#define RTHREADS  512

// recurrence v6 SMEM layout (floats)
#define WPAD   516
#define HSTR   516
#define BPADP  33
#define WS_TOT (32 * WPAD)
#define HF_TOT (32 * HSTR)
#define PT_TOT (4 * 32 * BPADP)
#define HV_TOT (32 * 12)
#define RECUR6_SMEM ((WS_TOT + HF_TOT + PT_TOT + HV_TOT) * 4)

// mma_gemm: CTA tile 128(M) x 64(N), K-chunk 32, double buffered
// buffer layout (bytes): Ah[128x32bf16]=8192 | Al=8192 | Wh[64x32]=4096 | Wl=4096
#define MG_BUF   24576
#define MG_SMEM  (2 * MG_BUF)

typedef unsigned long long u64;

// ------------------------- device scratch -------------------------
__device__ float g_Whh0[G * H];
__device__ float g_Whh1[G * H];
__device__ float g_bias0[G];
__device__ float g_bias1[G];
__device__ float g_xW[(size_t)T * B * G];     // [t*B+b][G]
__device__ float g_hseq[(size_t)T * B * H];   // layer0 h sequence
__device__ float g_h[2][B * H];               // layer1 double-buffered h
__device__ unsigned int g_bar2[2][16];
// bf16 hi/lo operands for tensor projections
__device__ __nv_bfloat16 g_Ah[(size_t)T * B * H];
__device__ __nv_bfloat16 g_Al[(size_t)T * B * H];
__device__ __nv_bfloat16 g_W0h[G * DIN], g_W0l[G * DIN];
__device__ __nv_bfloat16 g_W1h[G * H],   g_W1l[G * H];

// ------------------------- helpers -------------------------
__device__ __forceinline__ u64 f2pack(float x, float y) {
    u64 r; asm("mov.b64 %0, {%1, %2};" : "=l"(r) : "f"(x), "f"(y)); return r;
}
__device__ __forceinline__ float2 f2unpack(u64 v) {
    float2 r; asm("mov.b64 {%0, %1}, %2;" : "=f"(r.x), "=f"(r.y) : "l"(v)); return r;
}
__device__ __forceinline__ void ffma2(u64& d, u64 a, u64 b) {
    asm("fma.rn.f32x2 %0, %1, %2, %0;" : "+l"(d) : "l"(a), "l"(b));
}
__device__ __forceinline__ float sigmf(float x) {
    return 1.0f / (1.0f + __expf(-x));
}
__device__ __forceinline__ uint32_t smem_u32(const void* p) {
    uint32_t a;
    asm("{ .reg .u64 t; cvta.to.shared.u64 t, %1; cvt.u32.u64 %0, t; }" : "=r"(a) : "l"(p));
    return a;
}
__device__ __forceinline__ void ldsm4(uint32_t* r, uint32_t addr) {
    asm volatile("ldmatrix.sync.aligned.m8n8.x4.shared.b16 {%0,%1,%2,%3}, [%4];"
                 : "=r"(r[0]), "=r"(r[1]), "=r"(r[2]), "=r"(r[3]) : "r"(addr));
}
__device__ __forceinline__ void mma16816(float* d, const uint32_t* a, const uint32_t* b) {
    asm volatile(
        "mma.sync.aligned.m16n8k16.row.col.f32.bf16.bf16.f32 "
        "{%0,%1,%2,%3}, {%4,%5,%6,%7}, {%8,%9}, {%0,%1,%2,%3};"
        : "+f"(d[0]), "+f"(d[1]), "+f"(d[2]), "+f"(d[3])
        : "r"(a[0]), "r"(a[1]), "r"(a[2]), "r"(a[3]), "r"(b[0]), "r"(b[1]));
}

// ------------------------- prep -------------------------
__global__ void prep_kernel(const float* Wih0, const float* mih0,
                            const float* Whh0, const float* mhh0,
                            const float* bih0, const float* bhh0,
                            const float* Wih1, const float* mih1,
                            const float* Whh1, const float* mhh1,
                            const float* bih1, const float* bhh1)
{
    int idx0 = blockIdx.x * blockDim.x + threadIdx.x;
    int stride = gridDim.x * blockDim.x;
    for (int i = idx0; i < G * H; i += stride) g_Whh0[i] = Whh0[i] * mhh0[i];
    for (int i = idx0; i < G * H; i += stride) g_Whh1[i] = Whh1[i] * mhh1[i];
    for (int i = idx0; i < G * DIN; i += stride) {
        float v = Wih0[i] * mih0[i];
        __nv_bfloat16 h = __float2bfloat16(v);
        g_W0h[i] = h;
        g_W0l[i] = __float2bfloat16(v - __bfloat162float(h));
    }
    for (int i = idx0; i < G * H; i += stride) {
        float v = Wih1[i] * mih1[i];
        __nv_bfloat16 h = __float2bfloat16(v);
        g_W1h[i] = h;
        g_W1l[i] = __float2bfloat16(v - __bfloat162float(h));
    }
    for (int i = idx0; i < G; i += stride) {
        g_bias0[i] = bih0[i] + bhh0[i];
        g_bias1[i] = bih1[i] + bhh1[i];
    }
}

__global__ void reset_state() {
    int i = blockIdx.x * blockDim.x + threadIdx.x;
    if (i < B * H) { g_h[0][i] = 0.0f; g_h[1][i] = 0.0f; }
    if (i < 32) g_bar2[i >> 4][i & 15] = 0u;
}

// convert x [B,T,DIN] -> A hi/lo [t*B+b][DIN]
__global__ void convert_x(const float* __restrict__ x) {
    int i = blockIdx.x * blockDim.x + threadIdx.x;
    int n = T * B * DIN;
    for (; i < n; i += gridDim.x * blockDim.x) {
        int m = i / DIN, k = i - m * DIN;
        int b = m & (B - 1), t = m >> 6;
        float v = x[(size_t)(b * T + t) * DIN + k];
        __nv_bfloat16 h = __float2bfloat16(v);
        g_Ah[i] = h;
        g_Al[i] = __float2bfloat16(v - __bfloat162float(h));
    }
}

// convert hseq [t*B+b][H] -> A hi/lo (same layout)
__global__ void convert_h() {
    int i = blockIdx.x * blockDim.x + threadIdx.x;
    int n = T * B * H;
    for (; i < n; i += gridDim.x * blockDim.x) {
        float v = g_hseq[i];
        __nv_bfloat16 h = __float2bfloat16(v);
        g_Ah[i] = h;
        g_Al[i] = __float2bfloat16(v - __bfloat162float(h));
    }
}

// ------------------------- warp-MMA projection GEMM -------------------------
// C[m][n] = sum_k A[m][k]*W[n][k] + bias[n]; split-bf16 fused in k-loop:
// acc += Ah*Wh + Al*Wh + Ah*Wl (fp32 accum).
// CTA 128(M) x 64(N), 8 warps (4M x 2N, warp tile 32x32), K-chunks of 32.
// SMEM swizzle: 64B rows, 16B chunk c -> c ^ ((row>>1)&3)  (conflict-free for
// both STS.128 staging waves and every ldmatrix phase).
__global__ void __launch_bounds__(256) mma_gemm(
    const __nv_bfloat16* __restrict__ Ah, const __nv_bfloat16* __restrict__ Al,
    const __nv_bfloat16* __restrict__ Wh, const __nv_bfloat16* __restrict__ Wl,
    const float* __restrict__ bias, float* __restrict__ C, int K)
{
    extern __shared__ char smc[];
    __shared__ float s_bias[64];

    const int tid = threadIdx.x;
    const int w   = tid >> 5;
    const int ln  = tid & 31;
    const int m0  = blockIdx.y << 7;
    const int n0  = blockIdx.x << 6;
    const int mw  = (w >> 1) << 5;    // warp M offset (0,32,64,96)
    const int nw  = (w & 1) << 5;     // warp N offset (0,32)

    if (tid < 64) s_bias[tid] = __ldg(&bias[n0 + tid]);

    const uint32_t ub = smem_u32(smc);

    // ---- staging precompute (gmem-coalesced rows, swizzled SMEM) ----
    int a_s[2]; size_t a_g[2];
#pragma unroll
    for (int i = 0; i < 2; i++) {
        int u  = tid + 256 * i;
        int ar = u >> 2, ac = u & 3;
        a_s[i] = ar * 64 + ((ac ^ ((ar >> 1) & 3)) << 4);
        a_g[i] = (size_t)(m0 + ar) * K + ac * 8;
    }
    const int wr  = tid >> 2, wc2 = tid & 3;
    const int w_s = wr * 64 + ((wc2 ^ ((wr >> 1) & 3)) << 4);
    const size_t w_g = (size_t)(n0 + wr) * K + wc2 * 8;

    // ---- ldmatrix lane constants ----
    const int arl  = (ln & 7) + ((ln >> 3) & 1) * 8;  // A: bit3 -> +8 row
    const int akh  = (ln >> 4) & 1;                   // A: bit4 -> k+8
    const int swzA = (arl >> 1) & 3;
    const int brl  = (ln & 7) + ((ln >> 4) & 1) * 8;  // B: bit4 -> +8 row(n)
    const int bkh  = (ln >> 3) & 1;                   // B: bit3 -> k+8
    const int swzB = (brl >> 1) & 3;

    float acc[2][4][4];
#pragma unroll
    for (int mi = 0; mi < 2; mi++)
#pragma unroll
        for (int nj = 0; nj < 4; nj++)
#pragma unroll
            for (int q = 0; q < 4; q++) acc[mi][nj][q] = 0.0f;

    const int NC = K >> 5;

    // ---- stage chunk 0 ----
    {
        char* bp = smc;
#pragma unroll
        for (int i = 0; i < 2; i++) {
            uint4 vh = __ldg((const uint4*)(Ah + a_g[i]));
            uint4 vl = __ldg((const uint4*)(Al + a_g[i]));
            *(uint4*)(bp + a_s[i])        = vh;
            *(uint4*)(bp + 8192 + a_s[i]) = vl;
        }
        uint4 wh = __ldg((const uint4*)(Wh + w_g));
        uint4 wl = __ldg((const uint4*)(Wl + w_g));
        *(uint4*)(bp + 16384 + w_s) = wh;
        *(uint4*)(bp + 20480 + w_s) = wl;
    }
    __syncthreads();

    for (int c = 0; c < NC; c++) {
        uint4 rah[2], ral[2], rwh, rwl;
        if (c + 1 < NC) {
            size_t ko = (size_t)(c + 1) * 32;
#pragma unroll
            for (int i = 0; i < 2; i++) {
                rah[i] = __ldg((const uint4*)(Ah + a_g[i] + ko));
                ral[i] = __ldg((const uint4*)(Al + a_g[i] + ko));
            }
            rwh = __ldg((const uint4*)(Wh + w_g + ko));
            rwl = __ldg((const uint4*)(Wl + w_g + ko));
        }

        const uint32_t base = ub + (uint32_t)(c & 1) * MG_BUF;
#pragma unroll
        for (int s = 0; s < 2; s++) {
            uint32_t fah[2][4], fal[2][4], fbh[2][4], fbl[2][4];
#pragma unroll
            for (int mi = 0; mi < 2; mi++) {
                int row = mw + mi * 16 + arl;
                uint32_t off = row * 64 + (((2 * s + akh) ^ swzA) << 4);
                ldsm4(fah[mi], base + off);
                ldsm4(fal[mi], base + 8192 + off);
            }
#pragma unroll
            for (int nj2 = 0; nj2 < 2; nj2++) {
                int row = nw + nj2 * 16 + brl;
                uint32_t off = row * 64 + (((2 * s + bkh) ^ swzB) << 4);
                ldsm4(fbh[nj2], base + 16384 + off);
                ldsm4(fbl[nj2], base + 20480 + off);
            }
#pragma unroll
            for (int mi = 0; mi < 2; mi++)
#pragma unroll
                for (int nj2 = 0; nj2 < 2; nj2++)
#pragma unroll
                    for (int hh = 0; hh < 2; hh++) {
                        float* d = acc[mi][nj2 * 2 + hh];
                        mma16816(d, fah[mi], &fbh[nj2][hh * 2]);
                        mma16816(d, fal[mi], &fbh[nj2][hh * 2]);
                        mma16816(d, fah[mi], &fbl[nj2][hh * 2]);
                    }
        }

        if (c + 1 < NC) {
            char* bp = smc + ((c + 1) & 1) * MG_BUF;
#pragma unroll
            for (int i = 0; i < 2; i++) {
                *(uint4*)(bp + a_s[i])        = rah[i];
                *(uint4*)(bp + 8192 + a_s[i]) = ral[i];
            }
            *(uint4*)(bp + 16384 + w_s) = rwh;
            *(uint4*)(bp + 20480 + w_s) = rwl;
            __syncthreads();
        }
    }

    // ---- epilogue: c-frag thread t -> rows g,g+8; cols 2(t%4) ----
    const int er = ln >> 2;
    const int ec = (ln & 3) * 2;
#pragma unroll
    for (int mi = 0; mi < 2; mi++) {
#pragma unroll
        for (int nj = 0; nj < 4; nj++) {
            int row = m0 + mw + mi * 16 + er;
            int cl  = nw + nj * 8 + ec;
            float b0 = s_bias[cl], b1 = s_bias[cl + 1];
            float2 o0 = make_float2(acc[mi][nj][0] + b0, acc[mi][nj][1] + b1);
            float2 o1 = make_float2(acc[mi][nj][2] + b0, acc[mi][nj][3] + b1);
            *(float2*)&C[(size_t)row * G + n0 + cl]       = o0;
            *(float2*)&C[(size_t)(row + 8) * G + n0 + cl] = o1;
        }
    }
}

// ------------------------- recurrence v6 (unchanged from R6) -------------------------
__global__ void __launch_bounds__(RTHREADS, 1) recur_kernel(float* outArg, int layer)
{
    extern __shared__ float sm[];
    float* Ws    = sm;
    float* hfull = Ws + WS_TOT;
    float* part  = hfull + HF_TOT;
    float* hvb   = part + PT_TOT;

    const float* Whh = layer ? g_Whh1 : g_Whh0;
    const int tid = threadIdx.x;
    const int w   = tid >> 5;
    const int ln  = tid & 31;
    const int rg  = w >> 2;
    const int kq  = w & 3;
    const int ks  = ln >> 3;
    const int bq  = ln & 7;
    const int uTile = blockIdx.x >> 1;
    const int bh    = blockIdx.x & 1;
    const int unit0 = uTile * 8;
    const int bb0   = bh * 32;
    unsigned int* barp = &g_bar2[bh][0];

    for (int i = tid; i < 32 * 128; i += RTHREADS) {
        int r   = i >> 7;
        int kc4 = i & 127;
        int u   = r >> 2, g = r & 3;
        float4 v = __ldg((const float4*)(Whh + (size_t)(g * H + unit0 + u) * H + kc4 * 4));
        *(float4*)&Ws[r * WPAD + kc4 * 4] = v;
    }

    const float* Wwarp = Ws + rg * 8 * WPAD;
    const int klocal = kq * 32 + ks * 8;
    const int sb = tid >> 4;
    const int sq = (tid & 15) * 4;
    const int ul = tid >> 5;
    const int ab = tid & 31;
    float creg = 0.0f;

    float* outp = layer ? outArg : (float*)0;

    for (int t = 0; t < T; t++) {
        const float* hin;
        if (layer == 0) hin = (t == 0) ? g_h[0] : (g_hseq + (size_t)(t - 1) * B * H);
        else            hin = g_h[t & 1];
        float* hout = layer ? g_h[(t + 1) & 1] : (g_hseq + (size_t)t * B * H);
        const float* xwt = g_xW + (size_t)t * B * G;

        float xg0 = 0.f, xg1 = 0.f, xg2 = 0.f, xg3 = 0.f;
        if (tid < 256) {
            xg0 = __ldg(&xwt[(bb0 + ab) * G + 0 * H + unit0 + ul]);
            xg1 = __ldg(&xwt[(bb0 + ab) * G + 1 * H + unit0 + ul]);
            xg2 = __ldg(&xwt[(bb0 + ab) * G + 2 * H + unit0 + ul]);
            xg3 = __ldg(&xwt[(bb0 + ab) * G + 3 * H + unit0 + ul]);
        }

        {
            const float* hrow = hin + (size_t)(bb0 + sb) * H + sq;
            float4 hv[8];
#pragma unroll
            for (int j = 0; j < 8; j++)
                hv[j] = __ldcg((const float4*)(hrow + j * 64));
            float* srow = hfull + sb * HSTR + sq;
#pragma unroll
            for (int j = 0; j < 8; j++)
                *(float4*)(srow + j * 64) = hv[j];
        }
        __syncthreads();

        u64 acc[8][4];
#pragma unroll
        for (int j = 0; j < 8; j++)
#pragma unroll
            for (int i = 0; i < 4; i++) acc[j][i] = 0ULL;

#pragma unroll
        for (int c = 0; c < 4; c++) {
            const float* hc = hfull + c * 128 + klocal;
            const float* wc = Wwarp + c * 128 + klocal;
#pragma unroll
            for (int k4 = 0; k4 < 2; k4++) {
                ulonglong2 hp[4];
#pragma unroll
                for (int i = 0; i < 4; i++)
                    hp[i] = *(const ulonglong2*)(hc + (bq + 8 * i) * HSTR + k4 * 4);
#pragma unroll
                for (int hhalf = 0; hhalf < 2; hhalf++) {
                    ulonglong2 wp[4];
#pragma unroll
                    for (int j = 0; j < 4; j++)
                        wp[j] = *(const ulonglong2*)(wc + (hhalf * 4 + j) * WPAD + k4 * 4);
#pragma unroll
                    for (int j = 0; j < 4; j++) {
#pragma unroll
                        for (int i = 0; i < 4; i++) {
                            ffma2(acc[hhalf * 4 + j][i], wp[j].x, hp[i].x);
                            ffma2(acc[hhalf * 4 + j][i], wp[j].y, hp[i].y);
                        }
                    }
                }
            }
        }

        float v[8][4];
#pragma unroll
        for (int j = 0; j < 8; j++)
#pragma unroll
            for (int i = 0; i < 4; i++) {
                float2 s = f2unpack(acc[j][i]);
                v[j][i] = s.x + s.y;
            }
#pragma unroll
        for (int j = 0; j < 8; j++)
#pragma unroll
            for (int i = 0; i < 4; i++) {
                v[j][i] += __shfl_xor_sync(0xffffffffu, v[j][i], 8);
                v[j][i] += __shfl_xor_sync(0xffffffffu, v[j][i], 16);
            }
        {
            float* pb = part + kq * (32 * BPADP);
#pragma unroll
            for (int jj = 0; jj < 2; jj++) {
                int j = ks * 2 + jj;
                float* pr = pb + (rg * 8 + j) * BPADP;
#pragma unroll
                for (int i = 0; i < 4; i++)
                    pr[bq + 8 * i] = v[j][i];
            }
        }
        __syncthreads();

        if (tid < 256) {
            float gate[4];
#pragma unroll
            for (int g = 0; g < 4; g++) {
                int r = ul * 4 + g;
                gate[g] = part[0 * 32 * BPADP + r * BPADP + ab]
                        + part[1 * 32 * BPADP + r * BPADP + ab]
                        + part[2 * 32 * BPADP + r * BPADP + ab]
                        + part[3 * 32 * BPADP + r * BPADP + ab];
            }
            float gi = gate[0] + xg0, gf = gate[1] + xg1;
            float gg = gate[2] + xg2, go = gate[3] + xg3;
            creg = sigmf(gf) * creg + sigmf(gi) * __tanhf(gg);
            float hv = sigmf(go) * __tanhf(creg);
            hvb[ab * 12 + ul] = hv;
        }
        __syncthreads();

        if (tid < 64) {
            int b  = tid >> 1;
            int hf = tid & 1;
            float4 vv = *(const float4*)&hvb[b * 12 + hf * 4];
            __stcg((float4*)(hout + (size_t)(bb0 + b) * H + unit0 + hf * 4), vv);
            if (outp && t == T - 1)
                __stcg((float4*)(outp + (size_t)(bb0 + b) * H + unit0 + hf * 4), vv);
        }

        if (t + 1 < T) {
            __syncthreads();
            if (tid == 0) {
                unsigned int one = 1u;
                asm volatile("red.release.gpu.global.add.u32 [%0], %1;"
                             :: "l"(barp), "r"(one) : "memory");
                unsigned int want = (unsigned int)(t + 1) * 64u;
                unsigned int vv;
                do {
                    asm volatile("ld.acquire.gpu.global.u32 %0, [%1];"
                                 : "=r"(vv) : "l"(barp));
                } while (vv < want);
            }
            __syncthreads();
        }
    }
}

// ------------------------- launch -------------------------
extern "C" void kernel_launch(void* const* d_in, const int* in_sizes, int n_in,
                              void* d_out, int out_size)
{
    (void)in_sizes; (void)n_in; (void)out_size;
    const float* x = (const float*)d_in[0];

    cudaFuncSetAttribute(recur_kernel, cudaFuncAttributeMaxDynamicSharedMemorySize, RECUR6_SMEM);
    cudaFuncSetAttribute(mma_gemm,     cudaFuncAttributeMaxDynamicSharedMemorySize, MG_SMEM);

    prep_kernel<<<512, 256>>>(
        (const float*)d_in[1],  (const float*)d_in[5],
        (const float*)d_in[2],  (const float*)d_in[6],
        (const float*)d_in[3],  (const float*)d_in[4],
        (const float*)d_in[7],  (const float*)d_in[11],
        (const float*)d_in[8],  (const float*)d_in[12],
        (const float*)d_in[9],  (const float*)d_in[10]);

    float* bias0; cudaGetSymbolAddress((void**)&bias0, g_bias0);
    float* bias1; cudaGetSymbolAddress((void**)&bias1, g_bias1);
    float* xW;    cudaGetSymbolAddress((void**)&xW,    g_xW);
    __nv_bfloat16 *Ah, *Al, *W0h, *W0l, *W1h, *W1l;
    cudaGetSymbolAddress((void**)&Ah,  g_Ah);
    cudaGetSymbolAddress((void**)&Al,  g_Al);
    cudaGetSymbolAddress((void**)&W0h, g_W0h);
    cudaGetSymbolAddress((void**)&W0l, g_W0l);
    cudaGetSymbolAddress((void**)&W1h, g_W1h);
    cudaGetSymbolAddress((void**)&W1l, g_W1l);

    dim3 mgrid(G / 64, (T * B) / 128);

    // layer 0
    convert_x<<<512, 256>>>(x);
    reset_state<<<(B * H + 255) / 256, 256>>>();
    mma_gemm<<<mgrid, 256, MG_SMEM>>>(Ah, Al, W0h, W0l, bias0, xW, DIN);
    recur_kernel<<<NCTA, RTHREADS, RECUR6_SMEM>>>((float*)0, 0);

    // layer 1
    convert_h<<<512, 256>>>();
    reset_state<<<(B * H + 255) / 256, 256>>>();
    mma_gemm<<<mgrid, 256, MG_SMEM>>>(Ah, Al, W1h, W1l, bias1, xW, H);
    recur_kernel<<<NCTA, RTHREADS, RECUR6_SMEM>>>((float*)d_out, 1);
}

// round 9
// speedup vs baseline: 1.7372x; 1.2905x over previous
#include <cuda_runtime.h>
#include <cuda_bf16.h>
#include <cstdint>

// Problem constants
#define B    64
#define T    512
#define DIN  256
#define H    512
#define G    2048   // 4*H

#define NCTA 128

// mma_gemm tile config (proven R8)
#define MG_BUF   24576
#define MG_SMEM  (2 * MG_BUF)

// recur_tc SMEM layout (bytes)
//  Whi 32*1024 @0 | Wlo @32768 | Hhi @65536 | Hlo @98304 | part(4*32*34 fp32) @131072
#define RT_PART_OFF 131072
#define RT_SMEM     (131072 + 4 * 32 * 34 * 4)   // 148480

typedef unsigned long long u64;

// ------------------------- device scratch -------------------------
__device__ float g_Whh0[G * H];
__device__ float g_Whh1[G * H];
__device__ float g_bias0[G];
__device__ float g_bias1[G];
__device__ float g_xW[(size_t)T * B * G];            // [t*B+b][G]
__device__ unsigned int g_bar2[2][16];
// bf16 hi/lo activations: x (layer0 input) then layer0 h-sequence
__device__ __nv_bfloat16 g_Ah[(size_t)T * B * H];
__device__ __nv_bfloat16 g_Al[(size_t)T * B * H];
// layer1 double-buffered h state (bf16 hi/lo); buf[0] doubles as the t=0 zeros
__device__ __nv_bfloat16 g_h1h[2][B * H];
__device__ __nv_bfloat16 g_h1l[2][B * H];
// masked+split input-projection weights
__device__ __nv_bfloat16 g_W0h[G * DIN], g_W0l[G * DIN];
__device__ __nv_bfloat16 g_W1h[G * H],   g_W1l[G * H];

// ------------------------- helpers -------------------------
__device__ __forceinline__ float sigmf(float x) {
    return 1.0f / (1.0f + __expf(-x));
}
__device__ __forceinline__ uint32_t smem_u32(const void* p) {
    uint32_t a;
    asm("{ .reg .u64 t; cvta.to.shared.u64 t, %1; cvt.u32.u64 %0, t; }" : "=r"(a) : "l"(p));
    return a;
}
__device__ __forceinline__ void ldsm4(uint32_t* r, uint32_t addr) {
    asm volatile("ldmatrix.sync.aligned.m8n8.x4.shared.b16 {%0,%1,%2,%3}, [%4];"
                 : "=r"(r[0]), "=r"(r[1]), "=r"(r[2]), "=r"(r[3]) : "r"(addr));
}
__device__ __forceinline__ void mma16816(float* d, const uint32_t* a, const uint32_t* b) {
    asm volatile(
        "mma.sync.aligned.m16n8k16.row.col.f32.bf16.bf16.f32 "
        "{%0,%1,%2,%3}, {%4,%5,%6,%7}, {%8,%9}, {%0,%1,%2,%3};"
        : "+f"(d[0]), "+f"(d[1]), "+f"(d[2]), "+f"(d[3])
        : "r"(a[0]), "r"(a[1]), "r"(a[2]), "r"(a[3]), "r"(b[0]), "r"(b[1]));
}
__device__ __forceinline__ void st_bf16_cg(__nv_bfloat16* p, __nv_bfloat16 v) {
    unsigned short u = *(unsigned short*)&v;
    asm volatile("st.global.cg.u16 [%0], %1;" :: "l"(p), "h"(u) : "memory");
}

// ------------------------- prep -------------------------
__global__ void prep_kernel(const float* Wih0, const float* mih0,
                            const float* Whh0, const float* mhh0,
                            const float* bih0, const float* bhh0,
                            const float* Wih1, const float* mih1,
                            const float* Whh1, const float* mhh1,
                            const float* bih1, const float* bhh1)
{
    int idx0 = blockIdx.x * blockDim.x + threadIdx.x;
    int stride = gridDim.x * blockDim.x;
    for (int i = idx0; i < G * H; i += stride) g_Whh0[i] = Whh0[i] * mhh0[i];
    for (int i = idx0; i < G * H; i += stride) g_Whh1[i] = Whh1[i] * mhh1[i];
    for (int i = idx0; i < G * DIN; i += stride) {
        float v = Wih0[i] * mih0[i];
        __nv_bfloat16 h = __float2bfloat16(v);
        g_W0h[i] = h;
        g_W0l[i] = __float2bfloat16(v - __bfloat162float(h));
    }
    for (int i = idx0; i < G * H; i += stride) {
        float v = Wih1[i] * mih1[i];
        __nv_bfloat16 h = __float2bfloat16(v);
        g_W1h[i] = h;
        g_W1l[i] = __float2bfloat16(v - __bfloat162float(h));
    }
    for (int i = idx0; i < G; i += stride) {
        g_bias0[i] = bih0[i] + bhh0[i];
        g_bias1[i] = bih1[i] + bhh1[i];
    }
}

__global__ void reset_state() {
    int i = blockIdx.x * blockDim.x + threadIdx.x;
    if (i < B * H) {
        __nv_bfloat16 z = __float2bfloat16(0.0f);
        g_h1h[0][i] = z; g_h1l[0][i] = z;
        g_h1h[1][i] = z; g_h1l[1][i] = z;
    }
    if (i < 32) g_bar2[i >> 4][i & 15] = 0u;
}

// convert x [B,T,DIN] -> hi/lo [t*B+b][DIN]
__global__ void convert_x(const float* __restrict__ x) {
    int i = blockIdx.x * blockDim.x + threadIdx.x;
    int n = T * B * DIN;
    for (; i < n; i += gridDim.x * blockDim.x) {
        int m = i / DIN, k = i - m * DIN;
        int b = m & (B - 1), t = m >> 6;
        float v = x[(size_t)(b * T + t) * DIN + k];
        __nv_bfloat16 h = __float2bfloat16(v);
        g_Ah[i] = h;
        g_Al[i] = __float2bfloat16(v - __bfloat162float(h));
    }
}

// ------------------------- warp-MMA projection GEMM (proven R8) -------------------------
__global__ void __launch_bounds__(256) mma_gemm(
    const __nv_bfloat16* __restrict__ Ah, const __nv_bfloat16* __restrict__ Al,
    const __nv_bfloat16* __restrict__ Wh, const __nv_bfloat16* __restrict__ Wl,
    const float* __restrict__ bias, float* __restrict__ C, int K)
{
    extern __shared__ char smc[];
    __shared__ float s_bias[64];

    const int tid = threadIdx.x;
    const int w   = tid >> 5;
    const int ln  = tid & 31;
    const int m0  = blockIdx.y << 7;
    const int n0  = blockIdx.x << 6;
    const int mw  = (w >> 1) << 5;
    const int nw  = (w & 1) << 5;

    if (tid < 64) s_bias[tid] = __ldg(&bias[n0 + tid]);

    const uint32_t ub = smem_u32(smc);

    int a_s[2]; size_t a_g[2];
#pragma unroll
    for (int i = 0; i < 2; i++) {
        int u  = tid + 256 * i;
        int ar = u >> 2, ac = u & 3;
        a_s[i] = ar * 64 + ((ac ^ ((ar >> 1) & 3)) << 4);
        a_g[i] = (size_t)(m0 + ar) * K + ac * 8;
    }
    const int wr  = tid >> 2, wc2 = tid & 3;
    const int w_s = wr * 64 + ((wc2 ^ ((wr >> 1) & 3)) << 4);
    const size_t w_g = (size_t)(n0 + wr) * K + wc2 * 8;

    const int arl  = (ln & 7) + ((ln >> 3) & 1) * 8;
    const int akh  = (ln >> 4) & 1;
    const int swzA = (arl >> 1) & 3;
    const int brl  = (ln & 7) + ((ln >> 4) & 1) * 8;
    const int bkh  = (ln >> 3) & 1;
    const int swzB = (brl >> 1) & 3;

    float acc[2][4][4];
#pragma unroll
    for (int mi = 0; mi < 2; mi++)
#pragma unroll
        for (int nj = 0; nj < 4; nj++)
#pragma unroll
            for (int q = 0; q < 4; q++) acc[mi][nj][q] = 0.0f;

    const int NC = K >> 5;

    {
        char* bp = smc;
#pragma unroll
        for (int i = 0; i < 2; i++) {
            uint4 vh = __ldg((const uint4*)(Ah + a_g[i]));
            uint4 vl = __ldg((const uint4*)(Al + a_g[i]));
            *(uint4*)(bp + a_s[i])        = vh;
            *(uint4*)(bp + 8192 + a_s[i]) = vl;
        }
        uint4 wh = __ldg((const uint4*)(Wh + w_g));
        uint4 wl = __ldg((const uint4*)(Wl + w_g));
        *(uint4*)(bp + 16384 + w_s) = wh;
        *(uint4*)(bp + 20480 + w_s) = wl;
    }
    __syncthreads();

    for (int c = 0; c < NC; c++) {
        uint4 rah[2], ral[2], rwh, rwl;
        if (c + 1 < NC) {
            size_t ko = (size_t)(c + 1) * 32;
#pragma unroll
            for (int i = 0; i < 2; i++) {
                rah[i] = __ldg((const uint4*)(Ah + a_g[i] + ko));
                ral[i] = __ldg((const uint4*)(Al + a_g[i] + ko));
            }
            rwh = __ldg((const uint4*)(Wh + w_g + ko));
            rwl = __ldg((const uint4*)(Wl + w_g + ko));
        }

        const uint32_t base = ub + (uint32_t)(c & 1) * MG_BUF;
#pragma unroll
        for (int s = 0; s < 2; s++) {
            uint32_t fah[2][4], fal[2][4], fbh[2][4], fbl[2][4];
#pragma unroll
            for (int mi = 0; mi < 2; mi++) {
                int row = mw + mi * 16 + arl;
                uint32_t off = row * 64 + (((2 * s + akh) ^ swzA) << 4);
                ldsm4(fah[mi], base + off);
                ldsm4(fal[mi], base + 8192 + off);
            }
#pragma unroll
            for (int nj2 = 0; nj2 < 2; nj2++) {
                int row = nw + nj2 * 16 + brl;
                uint32_t off = row * 64 + (((2 * s + bkh) ^ swzB) << 4);
                ldsm4(fbh[nj2], base + 16384 + off);
                ldsm4(fbl[nj2], base + 20480 + off);
            }
#pragma unroll
            for (int mi = 0; mi < 2; mi++)
#pragma unroll
                for (int nj2 = 0; nj2 < 2; nj2++)
#pragma unroll
                    for (int hh = 0; hh < 2; hh++) {
                        float* d = acc[mi][nj2 * 2 + hh];
                        mma16816(d, fah[mi], &fbh[nj2][hh * 2]);
                        mma16816(d, fal[mi], &fbh[nj2][hh * 2]);
                        mma16816(d, fah[mi], &fbl[nj2][hh * 2]);
                    }
        }

        if (c + 1 < NC) {
            char* bp = smc + ((c + 1) & 1) * MG_BUF;
#pragma unroll
            for (int i = 0; i < 2; i++) {
                *(uint4*)(bp + a_s[i])        = rah[i];
                *(uint4*)(bp + 8192 + a_s[i]) = ral[i];
            }
            *(uint4*)(bp + 16384 + w_s) = rwh;
            *(uint4*)(bp + 20480 + w_s) = rwl;
            __syncthreads();
        }
    }

    const int er = ln >> 2;
    const int ec = (ln & 3) * 2;
#pragma unroll
    for (int mi = 0; mi < 2; mi++) {
#pragma unroll
        for (int nj = 0; nj < 4; nj++) {
            int row = m0 + mw + mi * 16 + er;
            int cl  = nw + nj * 8 + ec;
            float b0 = s_bias[cl], b1 = s_bias[cl + 1];
            float2 o0 = make_float2(acc[mi][nj][0] + b0, acc[mi][nj][1] + b1);
            float2 o1 = make_float2(acc[mi][nj][2] + b0, acc[mi][nj][3] + b1);
            *(float2*)&C[(size_t)row * G + n0 + cl]       = o0;
            *(float2*)&C[(size_t)(row + 8) * G + n0 + cl] = o1;
        }
    }
}

// ------------------------- tensor-core recurrence -------------------------
// 128 CTAs = 16 unit-tiles(8 units) x 2 batch-halves? (8 units x 32 batches).
// A = W_hh rows (32 x 512 bf16 hi/lo, SMEM swizzled, converted once).
// B = h (32 x 512 bf16 hi/lo, staged per step).
// 16 warps = (mh 2) x (nh 2) x (kq 4); warp tile m16 n16 K128; fp32 accum;
// 3-product split; 4-way kq SMEM reduction; v6 activation/barrier skeleton.
__global__ void __launch_bounds__(512, 1) recur_tc(float* outArg, int layer)
{
    extern __shared__ char smraw[];
    char*  Whi = smraw;
    char*  Wlo = smraw + 32768;
    char*  Hhi = smraw + 65536;
    char*  Hlo = smraw + 98304;
    float* part = (float*)(smraw + RT_PART_OFF);   // [4 kq][32 row][34]

    const float* Whh = layer ? g_Whh1 : g_Whh0;
    const int tid = threadIdx.x;
    const int w   = tid >> 5;
    const int ln  = tid & 31;
    const int mh  = w >> 3;           // m half: rows mh*16..+15
    const int nh  = (w >> 2) & 1;     // n half: batches nh*16..+15
    const int kq  = w & 3;            // K quarter: k = kq*128..+127
    const int unit0 = (blockIdx.x >> 1) * 8;
    const int bh    = blockIdx.x & 1;
    const int bb0   = bh * 32;
    unsigned int* barp = &g_bar2[bh][0];

    // ---- convert + stage W_hh (rows r = u*4 + g) into swizzled SMEM, once ----
    for (int i = tid; i < 32 * 512; i += 512) {
        int r = i >> 9, k = i & 511;
        int u = r >> 2, g = r & 3;
        float v = __ldg(&Whh[(size_t)(g * H + unit0 + u) * H + k]);
        __nv_bfloat16 hi = __float2bfloat16(v);
        __nv_bfloat16 lo = __float2bfloat16(v - __bfloat162float(hi));
        int off = r * 1024 + (((k >> 3) ^ (r & 7)) << 4) + (k & 7) * 2;
        *(__nv_bfloat16*)(Whi + off) = hi;
        *(__nv_bfloat16*)(Wlo + off) = lo;
    }

    // ---- ldmatrix lane constants (R8-proven mapping) ----
    const int arl = (ln & 7) + ((ln >> 3) & 1) * 8;
    const int akh = (ln >> 4) & 1;
    const int brl = (ln & 7) + ((ln >> 4) & 1) * 8;
    const int bkh = (ln >> 3) & 1;
    const int rowA = mh * 16 + arl;
    const int rowB = nh * 16 + brl;
    const uint32_t baseWhi = smem_u32(Whi) + rowA * 1024;
    const uint32_t baseWlo = smem_u32(Wlo) + rowA * 1024;
    const uint32_t baseHhi = smem_u32(Hhi) + rowB * 1024;
    const uint32_t baseHlo = smem_u32(Hlo) + rowB * 1024;
    const int aX = rowA & 7;
    const int bX = rowB & 7;

    // epilogue frag coords
    const int er = ln >> 2;
    const int ec = (ln & 3) * 2;

    // staging roles: batch sb, chunk cj (+16j)
    const int sb = tid >> 4;
    const int cj = tid & 15;
    const uint32_t stOff = sb * 1024;

    // activation roles (tid < 256)
    const int ul = tid >> 5;
    const int ab = tid & 31;
    float creg = 0.0f;

    float* outp = layer ? outArg : (float*)0;

    for (int t = 0; t < T; t++) {
        const __nv_bfloat16 *hinh, *hinl;
        if (layer == 0) {
            hinh = (t == 0) ? g_h1h[0] : (g_Ah + (size_t)(t - 1) * B * H);
            hinl = (t == 0) ? g_h1l[0] : (g_Al + (size_t)(t - 1) * B * H);
        } else {
            hinh = g_h1h[t & 1];
            hinl = g_h1l[t & 1];
        }
        const float* xwt = g_xW + (size_t)t * B * G;

        // prefetch xW gates (consumed ~4K cyc later)
        float xg0 = 0.f, xg1 = 0.f, xg2 = 0.f, xg3 = 0.f;
        if (tid < 256) {
            xg0 = __ldg(&xwt[(bb0 + ab) * G + 0 * H + unit0 + ul]);
            xg1 = __ldg(&xwt[(bb0 + ab) * G + 1 * H + unit0 + ul]);
            xg2 = __ldg(&xwt[(bb0 + ab) * G + 2 * H + unit0 + ul]);
            xg3 = __ldg(&xwt[(bb0 + ab) * G + 3 * H + unit0 + ul]);
        }

        // ---- stage h hi/lo (32 b x 512) in one wave, swizzled ----
        {
            const uint4* gh = (const uint4*)(hinh + (size_t)(bb0 + sb) * H);
            const uint4* gl = (const uint4*)(hinl + (size_t)(bb0 + sb) * H);
            uint4 vh[4], vl[4];
#pragma unroll
            for (int j = 0; j < 4; j++) {
                int c4 = cj + 16 * j;
                vh[j] = __ldcg(gh + c4);
                vl[j] = __ldcg(gl + c4);
            }
#pragma unroll
            for (int j = 0; j < 4; j++) {
                int c4 = cj + 16 * j;
                uint32_t off = stOff + ((c4 ^ (sb & 7)) << 4);
                *(uint4*)(Hhi + off) = vh[j];
                *(uint4*)(Hlo + off) = vl[j];
            }
        }
        __syncthreads();

        // ---- MMA over this warp's K slice ----
        float d0[4] = {0, 0, 0, 0}, d1[4] = {0, 0, 0, 0};
#pragma unroll
        for (int i = 0; i < 8; i++) {
            int c2 = (kq * 8 + i) * 2;
            uint32_t fah[4], fal[4], fbh[4], fbl[4];
            uint32_t ca = (uint32_t)((c2 + akh) ^ aX) << 4;
            uint32_t cb = (uint32_t)((c2 + bkh) ^ bX) << 4;
            ldsm4(fah, baseWhi + ca);
            ldsm4(fal, baseWlo + ca);
            ldsm4(fbh, baseHhi + cb);
            ldsm4(fbl, baseHlo + cb);
            mma16816(d0, fah, &fbh[0]);
            mma16816(d1, fah, &fbh[2]);
            mma16816(d0, fal, &fbh[0]);
            mma16816(d1, fal, &fbh[2]);
            mma16816(d0, fah, &fbl[0]);
            mma16816(d1, fah, &fbl[2]);
        }

        // ---- write partials: part[kq][row][batch] ----
        {
            float* pb = part + kq * (32 * 34);
            int r0 = mh * 16 + er;
            int c0 = nh * 16 + ec;
            *(float2*)&pb[r0 * 34 + c0]           = make_float2(d0[0], d0[1]);
            *(float2*)&pb[(r0 + 8) * 34 + c0]     = make_float2(d0[2], d0[3]);
            *(float2*)&pb[r0 * 34 + c0 + 8]       = make_float2(d1[0], d1[1]);
            *(float2*)&pb[(r0 + 8) * 34 + c0 + 8] = make_float2(d1[2], d1[3]);
        }
        __syncthreads();

        // ---- activation: thread = (unit ul, batch ab), tid < 256 ----
        if (tid < 256) {
            float gate[4];
#pragma unroll
            for (int g = 0; g < 4; g++) {
                int r = ul * 4 + g;
                gate[g] = part[0 * 32 * 34 + r * 34 + ab]
                        + part[1 * 32 * 34 + r * 34 + ab]
                        + part[2 * 32 * 34 + r * 34 + ab]
                        + part[3 * 32 * 34 + r * 34 + ab];
            }
            float gi = gate[0] + xg0, gf = gate[1] + xg1;
            float gg = gate[2] + xg2, go = gate[3] + xg3;
            creg = sigmf(gf) * creg + sigmf(gi) * __tanhf(gg);
            float hv = sigmf(go) * __tanhf(creg);

            __nv_bfloat16 hhi = __float2bfloat16(hv);
            __nv_bfloat16 hlo = __float2bfloat16(hv - __bfloat162float(hhi));
            if (layer == 0) {
                size_t o = (size_t)(t * B + bb0 + ab) * H + unit0 + ul;
                st_bf16_cg(&g_Ah[o], hhi);
                st_bf16_cg(&g_Al[o], hlo);
            } else {
                size_t o = (size_t)(bb0 + ab) * H + unit0 + ul;
                st_bf16_cg(&g_h1h[(t + 1) & 1][o], hhi);
                st_bf16_cg(&g_h1l[(t + 1) & 1][o], hlo);
                if (t == T - 1) outp[o] = hv;
            }
        }

        // ---- per-half grid barrier (64 CTAs) ----
        if (t + 1 < T) {
            __syncthreads();
            if (tid == 0) {
                unsigned int one = 1u;
                asm volatile("red.release.gpu.global.add.u32 [%0], %1;"
                             :: "l"(barp), "r"(one) : "memory");
                unsigned int want = (unsigned int)(t + 1) * 64u;
                unsigned int vv;
                do {
                    asm volatile("ld.acquire.gpu.global.u32 %0, [%1];"
                                 : "=r"(vv) : "l"(barp));
                } while (vv < want);
            }
            __syncthreads();
        }
    }
}

// ------------------------- launch -------------------------
extern "C" void kernel_launch(void* const* d_in, const int* in_sizes, int n_in,
                              void* d_out, int out_size)
{
    (void)in_sizes; (void)n_in; (void)out_size;
    const float* x = (const float*)d_in[0];

    cudaFuncSetAttribute(mma_gemm, cudaFuncAttributeMaxDynamicSharedMemorySize, MG_SMEM);
    cudaFuncSetAttribute(recur_tc, cudaFuncAttributeMaxDynamicSharedMemorySize, RT_SMEM);

    prep_kernel<<<512, 256>>>(
        (const float*)d_in[1],  (const float*)d_in[5],
        (const float*)d_in[2],  (const float*)d_in[6],
        (const float*)d_in[3],  (const float*)d_in[4],
        (const float*)d_in[7],  (const float*)d_in[11],
        (const float*)d_in[8],  (const float*)d_in[12],
        (const float*)d_in[9],  (const float*)d_in[10]);

    float* bias0; cudaGetSymbolAddress((void**)&bias0, g_bias0);
    float* bias1; cudaGetSymbolAddress((void**)&bias1, g_bias1);
    float* xW;    cudaGetSymbolAddress((void**)&xW,    g_xW);
    __nv_bfloat16 *Ah, *Al, *W0h, *W0l, *W1h, *W1l;
    cudaGetSymbolAddress((void**)&Ah,  g_Ah);
    cudaGetSymbolAddress((void**)&Al,  g_Al);
    cudaGetSymbolAddress((void**)&W0h, g_W0h);
    cudaGetSymbolAddress((void**)&W0l, g_W0l);
    cudaGetSymbolAddress((void**)&W1h, g_W1h);
    cudaGetSymbolAddress((void**)&W1l, g_W1l);

    dim3 mgrid(G / 64, (T * B) / 128);

    // layer 0
    convert_x<<<512, 256>>>(x);
    reset_state<<<(B * H + 255) / 256, 256>>>();
    mma_gemm<<<mgrid, 256, MG_SMEM>>>(Ah, Al, W0h, W0l, bias0, xW, DIN);
    recur_tc<<<NCTA, 512, RT_SMEM>>>((float*)0, 0);

    // layer 1 (g_Ah/g_Al now hold layer0's h sequence — no convert needed)
    mma_gemm<<<mgrid, 256, MG_SMEM>>>(Ah, Al, W1h, W1l, bias1, xW, H);
    reset_state<<<(B * H + 255) / 256, 256>>>();
    recur_tc<<<NCTA, 512, RT_SMEM>>>((float*)d_out, 1);
}

// round 10
// speedup vs baseline: 1.8536x; 1.0670x over previous
#include <cuda_runtime.h>
#include <cuda_bf16.h>
#include <cstdint>

// Problem constants
#define B    64
#define T    512
#define DIN  256
#define H    512
#define G    2048   // 4*H

#define NCTA 128

// mma_gemm tile config (proven R8)
#define MG_BUF   24576
#define MG_SMEM  (2 * MG_BUF)

// recur_tc SMEM layout (bytes)
//  Whi 32*1024 @0 | Wlo @32768 | Hhi @65536 | Hlo @98304 | part(4*32*34 fp32) @131072
#define RT_PART_OFF 131072
#define RT_SMEM     (131072 + 4 * 32 * 34 * 4)   // 148480

typedef unsigned long long u64;

// ------------------------- device scratch -------------------------
__device__ float g_Whh0[G * H];
__device__ float g_Whh1[G * H];
__device__ float g_bias0[G];
__device__ float g_bias1[G];
__device__ float g_xW[(size_t)T * B * G];            // [t*B+b][G]
__device__ unsigned int g_bar2[2][16];
// bf16 hi/lo activations: x (layer0 input) then layer0 h-sequence
__device__ __nv_bfloat16 g_Ah[(size_t)T * B * H];
__device__ __nv_bfloat16 g_Al[(size_t)T * B * H];
// layer1 double-buffered h state (bf16 hi/lo); buf[0] doubles as the t=0 zeros
__device__ __nv_bfloat16 g_h1h[2][B * H];
__device__ __nv_bfloat16 g_h1l[2][B * H];
// masked+split input-projection weights
__device__ __nv_bfloat16 g_W0h[G * DIN], g_W0l[G * DIN];
__device__ __nv_bfloat16 g_W1h[G * H],   g_W1l[G * H];

// ------------------------- helpers -------------------------
__device__ __forceinline__ float sigmf(float x) {
    return 1.0f / (1.0f + __expf(-x));
}
__device__ __forceinline__ uint32_t smem_u32(const void* p) {
    uint32_t a;
    asm("{ .reg .u64 t; cvta.to.shared.u64 t, %1; cvt.u32.u64 %0, t; }" : "=r"(a) : "l"(p));
    return a;
}
__device__ __forceinline__ void ldsm4(uint32_t* r, uint32_t addr) {
    asm volatile("ldmatrix.sync.aligned.m8n8.x4.shared.b16 {%0,%1,%2,%3}, [%4];"
                 : "=r"(r[0]), "=r"(r[1]), "=r"(r[2]), "=r"(r[3]) : "r"(addr));
}
__device__ __forceinline__ void mma16816(float* d, const uint32_t* a, const uint32_t* b) {
    asm volatile(
        "mma.sync.aligned.m16n8k16.row.col.f32.bf16.bf16.f32 "
        "{%0,%1,%2,%3}, {%4,%5,%6,%7}, {%8,%9}, {%0,%1,%2,%3};"
        : "+f"(d[0]), "+f"(d[1]), "+f"(d[2]), "+f"(d[3])
        : "r"(a[0]), "r"(a[1]), "r"(a[2]), "r"(a[3]), "r"(b[0]), "r"(b[1]));
}
__device__ __forceinline__ void st_bf16_cg(__nv_bfloat16* p, __nv_bfloat16 v) {
    unsigned short u = *(unsigned short*)&v;
    asm volatile("st.global.cg.u16 [%0], %1;" :: "l"(p), "h"(u) : "memory");
}

// ------------------------- prep -------------------------
__global__ void prep_kernel(const float* Wih0, const float* mih0,
                            const float* Whh0, const float* mhh0,
                            const float* bih0, const float* bhh0,
                            const float* Wih1, const float* mih1,
                            const float* Whh1, const float* mhh1,
                            const float* bih1, const float* bhh1)
{
    int idx0 = blockIdx.x * blockDim.x + threadIdx.x;
    int stride = gridDim.x * blockDim.x;
    for (int i = idx0; i < G * H; i += stride) g_Whh0[i] = Whh0[i] * mhh0[i];
    for (int i = idx0; i < G * H; i += stride) g_Whh1[i] = Whh1[i] * mhh1[i];
    for (int i = idx0; i < G * DIN; i += stride) {
        float v = Wih0[i] * mih0[i];
        __nv_bfloat16 h = __float2bfloat16(v);
        g_W0h[i] = h;
        g_W0l[i] = __float2bfloat16(v - __bfloat162float(h));
    }
    for (int i = idx0; i < G * H; i += stride) {
        float v = Wih1[i] * mih1[i];
        __nv_bfloat16 h = __float2bfloat16(v);
        g_W1h[i] = h;
        g_W1l[i] = __float2bfloat16(v - __bfloat162float(h));
    }
    for (int i = idx0; i < G; i += stride) {
        g_bias0[i] = bih0[i] + bhh0[i];
        g_bias1[i] = bih1[i] + bhh1[i];
    }
}

__global__ void reset_state() {
    int i = blockIdx.x * blockDim.x + threadIdx.x;
    if (i < B * H) {
        __nv_bfloat16 z = __float2bfloat16(0.0f);
        g_h1h[0][i] = z; g_h1l[0][i] = z;
        g_h1h[1][i] = z; g_h1l[1][i] = z;
    }
    if (i < 32) g_bar2[i >> 4][i & 15] = 0u;
}

// convert x [B,T,DIN] -> hi/lo [t*B+b][DIN]
__global__ void convert_x(const float* __restrict__ x) {
    int i = blockIdx.x * blockDim.x + threadIdx.x;
    int n = T * B * DIN;
    for (; i < n; i += gridDim.x * blockDim.x) {
        int m = i / DIN, k = i - m * DIN;
        int b = m & (B - 1), t = m >> 6;
        float v = x[(size_t)(b * T + t) * DIN + k];
        __nv_bfloat16 h = __float2bfloat16(v);
        g_Ah[i] = h;
        g_Al[i] = __float2bfloat16(v - __bfloat162float(h));
    }
}

// ------------------------- warp-MMA projection GEMM (proven R8) -------------------------
__global__ void __launch_bounds__(256) mma_gemm(
    const __nv_bfloat16* __restrict__ Ah, const __nv_bfloat16* __restrict__ Al,
    const __nv_bfloat16* __restrict__ Wh, const __nv_bfloat16* __restrict__ Wl,
    const float* __restrict__ bias, float* __restrict__ C, int K)
{
    extern __shared__ char smc[];
    __shared__ float s_bias[64];

    const int tid = threadIdx.x;
    const int w   = tid >> 5;
    const int ln  = tid & 31;
    const int m0  = blockIdx.y << 7;
    const int n0  = blockIdx.x << 6;
    const int mw  = (w >> 1) << 5;
    const int nw  = (w & 1) << 5;

    if (tid < 64) s_bias[tid] = __ldg(&bias[n0 + tid]);

    const uint32_t ub = smem_u32(smc);

    int a_s[2]; size_t a_g[2];
#pragma unroll
    for (int i = 0; i < 2; i++) {
        int u  = tid + 256 * i;
        int ar = u >> 2, ac = u & 3;
        a_s[i] = ar * 64 + ((ac ^ ((ar >> 1) & 3)) << 4);
        a_g[i] = (size_t)(m0 + ar) * K + ac * 8;
    }
    const int wr  = tid >> 2, wc2 = tid & 3;
    const int w_s = wr * 64 + ((wc2 ^ ((wr >> 1) & 3)) << 4);
    const size_t w_g = (size_t)(n0 + wr) * K + wc2 * 8;

    const int arl  = (ln & 7) + ((ln >> 3) & 1) * 8;
    const int akh  = (ln >> 4) & 1;
    const int swzA = (arl >> 1) & 3;
    const int brl  = (ln & 7) + ((ln >> 4) & 1) * 8;
    const int bkh  = (ln >> 3) & 1;
    const int swzB = (brl >> 1) & 3;

    float acc[2][4][4];
#pragma unroll
    for (int mi = 0; mi < 2; mi++)
#pragma unroll
        for (int nj = 0; nj < 4; nj++)
#pragma unroll
            for (int q = 0; q < 4; q++) acc[mi][nj][q] = 0.0f;

    const int NC = K >> 5;

    {
        char* bp = smc;
#pragma unroll
        for (int i = 0; i < 2; i++) {
            uint4 vh = __ldg((const uint4*)(Ah + a_g[i]));
            uint4 vl = __ldg((const uint4*)(Al + a_g[i]));
            *(uint4*)(bp + a_s[i])        = vh;
            *(uint4*)(bp + 8192 + a_s[i]) = vl;
        }
        uint4 wh = __ldg((const uint4*)(Wh + w_g));
        uint4 wl = __ldg((const uint4*)(Wl + w_g));
        *(uint4*)(bp + 16384 + w_s) = wh;
        *(uint4*)(bp + 20480 + w_s) = wl;
    }
    __syncthreads();

    for (int c = 0; c < NC; c++) {
        uint4 rah[2], ral[2], rwh, rwl;
        if (c + 1 < NC) {
            size_t ko = (size_t)(c + 1) * 32;
#pragma unroll
            for (int i = 0; i < 2; i++) {
                rah[i] = __ldg((const uint4*)(Ah + a_g[i] + ko));
                ral[i] = __ldg((const uint4*)(Al + a_g[i] + ko));
            }
            rwh = __ldg((const uint4*)(Wh + w_g + ko));
            rwl = __ldg((const uint4*)(Wl + w_g + ko));
        }

        const uint32_t base = ub + (uint32_t)(c & 1) * MG_BUF;
#pragma unroll
        for (int s = 0; s < 2; s++) {
            uint32_t fah[2][4], fal[2][4], fbh[2][4], fbl[2][4];
#pragma unroll
            for (int mi = 0; mi < 2; mi++) {
                int row = mw + mi * 16 + arl;
                uint32_t off = row * 64 + (((2 * s + akh) ^ swzA) << 4);
                ldsm4(fah[mi], base + off);
                ldsm4(fal[mi], base + 8192 + off);
            }
#pragma unroll
            for (int nj2 = 0; nj2 < 2; nj2++) {
                int row = nw + nj2 * 16 + brl;
                uint32_t off = row * 64 + (((2 * s + bkh) ^ swzB) << 4);
                ldsm4(fbh[nj2], base + 16384 + off);
                ldsm4(fbl[nj2], base + 20480 + off);
            }
#pragma unroll
            for (int mi = 0; mi < 2; mi++)
#pragma unroll
                for (int nj2 = 0; nj2 < 2; nj2++)
#pragma unroll
                    for (int hh = 0; hh < 2; hh++) {
                        float* d = acc[mi][nj2 * 2 + hh];
                        mma16816(d, fah[mi], &fbh[nj2][hh * 2]);
                        mma16816(d, fal[mi], &fbh[nj2][hh * 2]);
                        mma16816(d, fah[mi], &fbl[nj2][hh * 2]);
                    }
        }

        if (c + 1 < NC) {
            char* bp = smc + ((c + 1) & 1) * MG_BUF;
#pragma unroll
            for (int i = 0; i < 2; i++) {
                *(uint4*)(bp + a_s[i])        = rah[i];
                *(uint4*)(bp + 8192 + a_s[i]) = ral[i];
            }
            *(uint4*)(bp + 16384 + w_s) = rwh;
            *(uint4*)(bp + 20480 + w_s) = rwl;
            __syncthreads();
        }
    }

    const int er = ln >> 2;
    const int ec = (ln & 3) * 2;
#pragma unroll
    for (int mi = 0; mi < 2; mi++) {
#pragma unroll
        for (int nj = 0; nj < 4; nj++) {
            int row = m0 + mw + mi * 16 + er;
            int cl  = nw + nj * 8 + ec;
            float b0 = s_bias[cl], b1 = s_bias[cl + 1];
            float2 o0 = make_float2(acc[mi][nj][0] + b0, acc[mi][nj][1] + b1);
            float2 o1 = make_float2(acc[mi][nj][2] + b0, acc[mi][nj][3] + b1);
            *(float2*)&C[(size_t)row * G + n0 + cl]       = o0;
            *(float2*)&C[(size_t)(row + 8) * G + n0 + cl] = o1;
        }
    }
}

// ------------------------- tensor-core recurrence (v2: W frags in registers) -------------------------
// 128 CTAs (8 units x 32 batches). A = W_hh (32x512 bf16 hi/lo) -> fragments
// hoisted into registers ONCE; per step only h fragments come through SMEM.
// 16 warps = (mh 2) x (nh 2) x (kq 4); warp tile m16 n16 K128; 3-product split.
__global__ void __launch_bounds__(512, 1) recur_tc(float* outArg, int layer)
{
    extern __shared__ char smraw[];
    char*  Whi = smraw;
    char*  Wlo = smraw + 32768;
    char*  Hhi = smraw + 65536;
    char*  Hlo = smraw + 98304;
    float* part = (float*)(smraw + RT_PART_OFF);   // [4 kq][32 row][34]

    const float* Whh = layer ? g_Whh1 : g_Whh0;
    const int tid = threadIdx.x;
    const int w   = tid >> 5;
    const int ln  = tid & 31;
    const int mh  = w >> 3;           // m half: rows mh*16..+15
    const int nh  = (w >> 2) & 1;     // n half: batches nh*16..+15
    const int kq  = w & 3;            // K quarter
    const int unit0 = (blockIdx.x >> 1) * 8;
    const int bh    = blockIdx.x & 1;
    const int bb0   = bh * 32;
    unsigned int* barp = &g_bar2[bh][0];

    // ---- convert + stage W_hh into swizzled SMEM (once) ----
    for (int i = tid; i < 32 * 512; i += 512) {
        int r = i >> 9, k = i & 511;
        int u = r >> 2, g = r & 3;
        float v = __ldg(&Whh[(size_t)(g * H + unit0 + u) * H + k]);
        __nv_bfloat16 hi = __float2bfloat16(v);
        __nv_bfloat16 lo = __float2bfloat16(v - __bfloat162float(hi));
        int off = r * 1024 + (((k >> 3) ^ (r & 7)) << 4) + (k & 7) * 2;
        *(__nv_bfloat16*)(Whi + off) = hi;
        *(__nv_bfloat16*)(Wlo + off) = lo;
    }
    __syncthreads();

    // ---- ldmatrix lane constants (R8-proven mapping) ----
    const int arl = (ln & 7) + ((ln >> 3) & 1) * 8;
    const int akh = (ln >> 4) & 1;
    const int brl = (ln & 7) + ((ln >> 4) & 1) * 8;
    const int bkh = (ln >> 3) & 1;
    const int rowA = mh * 16 + arl;
    const int rowB = nh * 16 + brl;
    const uint32_t baseWhi = smem_u32(Whi) + rowA * 1024;
    const uint32_t baseWlo = smem_u32(Wlo) + rowA * 1024;
    const uint32_t baseHhi = smem_u32(Hhi) + rowB * 1024;
    const uint32_t baseHlo = smem_u32(Hlo) + rowB * 1024;
    const int aX = rowA & 7;
    const int bX = rowB & 7;

    // ---- hoist W fragments into registers (step-invariant) ----
    uint32_t wfh[8][4], wfl[8][4];
#pragma unroll
    for (int i = 0; i < 8; i++) {
        int c2 = (kq * 8 + i) * 2;
        uint32_t ca = (uint32_t)((c2 + akh) ^ aX) << 4;
        ldsm4(wfh[i], baseWhi + ca);
        ldsm4(wfl[i], baseWlo + ca);
    }

    // epilogue frag coords
    const int er = ln >> 2;
    const int ec = (ln & 3) * 2;

    // staging roles
    const int sb = tid >> 4;
    const int cj = tid & 15;
    const uint32_t stOff = sb * 1024;

    // activation roles (tid < 256)
    const int ul = tid >> 5;
    const int ab = tid & 31;
    float creg = 0.0f;

    float* outp = layer ? outArg : (float*)0;

    for (int t = 0; t < T; t++) {
        const __nv_bfloat16 *hinh, *hinl;
        if (layer == 0) {
            hinh = (t == 0) ? g_h1h[0] : (g_Ah + (size_t)(t - 1) * B * H);
            hinl = (t == 0) ? g_h1l[0] : (g_Al + (size_t)(t - 1) * B * H);
        } else {
            hinh = g_h1h[t & 1];
            hinl = g_h1l[t & 1];
        }
        const float* xwt = g_xW + (size_t)t * B * G;

        float xg0 = 0.f, xg1 = 0.f, xg2 = 0.f, xg3 = 0.f;
        if (tid < 256) {
            xg0 = __ldg(&xwt[(bb0 + ab) * G + 0 * H + unit0 + ul]);
            xg1 = __ldg(&xwt[(bb0 + ab) * G + 1 * H + unit0 + ul]);
            xg2 = __ldg(&xwt[(bb0 + ab) * G + 2 * H + unit0 + ul]);
            xg3 = __ldg(&xwt[(bb0 + ab) * G + 3 * H + unit0 + ul]);
        }

        // ---- stage h hi/lo (32 b x 512), swizzled, one wave ----
        {
            const uint4* gh = (const uint4*)(hinh + (size_t)(bb0 + sb) * H);
            const uint4* gl = (const uint4*)(hinl + (size_t)(bb0 + sb) * H);
            uint4 vh[4], vl[4];
#pragma unroll
            for (int j = 0; j < 4; j++) {
                int c4 = cj + 16 * j;
                vh[j] = __ldcg(gh + c4);
                vl[j] = __ldcg(gl + c4);
            }
#pragma unroll
            for (int j = 0; j < 4; j++) {
                int c4 = cj + 16 * j;
                uint32_t off = stOff + ((c4 ^ (sb & 7)) << 4);
                *(uint4*)(Hhi + off) = vh[j];
                *(uint4*)(Hlo + off) = vl[j];
            }
        }
        __syncthreads();

        // ---- MMA (h frags from SMEM, W frags from regs) ----
        float d0[4] = {0, 0, 0, 0}, d1[4] = {0, 0, 0, 0};
#pragma unroll
        for (int i = 0; i < 8; i++) {
            int c2 = (kq * 8 + i) * 2;
            uint32_t fbh[4], fbl[4];
            uint32_t cb = (uint32_t)((c2 + bkh) ^ bX) << 4;
            ldsm4(fbh, baseHhi + cb);
            ldsm4(fbl, baseHlo + cb);
            mma16816(d0, wfh[i], &fbh[0]);
            mma16816(d1, wfh[i], &fbh[2]);
            mma16816(d0, wfl[i], &fbh[0]);
            mma16816(d1, wfl[i], &fbh[2]);
            mma16816(d0, wfh[i], &fbl[0]);
            mma16816(d1, wfh[i], &fbl[2]);
        }

        // ---- write partials: part[kq][row][batch] ----
        {
            float* pb = part + kq * (32 * 34);
            int r0 = mh * 16 + er;
            int c0 = nh * 16 + ec;
            *(float2*)&pb[r0 * 34 + c0]           = make_float2(d0[0], d0[1]);
            *(float2*)&pb[(r0 + 8) * 34 + c0]     = make_float2(d0[2], d0[3]);
            *(float2*)&pb[r0 * 34 + c0 + 8]       = make_float2(d1[0], d1[1]);
            *(float2*)&pb[(r0 + 8) * 34 + c0 + 8] = make_float2(d1[2], d1[3]);
        }
        __syncthreads();

        // ---- activation: thread = (unit ul, batch ab), tid < 256 ----
        if (tid < 256) {
            float gate[4];
#pragma unroll
            for (int g = 0; g < 4; g++) {
                int r = ul * 4 + g;
                gate[g] = part[0 * 32 * 34 + r * 34 + ab]
                        + part[1 * 32 * 34 + r * 34 + ab]
                        + part[2 * 32 * 34 + r * 34 + ab]
                        + part[3 * 32 * 34 + r * 34 + ab];
            }
            float gi = gate[0] + xg0, gf = gate[1] + xg1;
            float gg = gate[2] + xg2, go = gate[3] + xg3;
            creg = sigmf(gf) * creg + sigmf(gi) * __tanhf(gg);
            float hv = sigmf(go) * __tanhf(creg);

            __nv_bfloat16 hhi = __float2bfloat16(hv);
            __nv_bfloat16 hlo = __float2bfloat16(hv - __bfloat162float(hhi));
            if (layer == 0) {
                size_t o = (size_t)(t * B + bb0 + ab) * H + unit0 + ul;
                st_bf16_cg(&g_Ah[o], hhi);
                st_bf16_cg(&g_Al[o], hlo);
            } else {
                size_t o = (size_t)(bb0 + ab) * H + unit0 + ul;
                st_bf16_cg(&g_h1h[(t + 1) & 1][o], hhi);
                st_bf16_cg(&g_h1l[(t + 1) & 1][o], hlo);
                if (t == T - 1) outp[o] = hv;
            }
        }

        // ---- per-half grid barrier (64 CTAs) ----
        if (t + 1 < T) {
            __syncthreads();
            if (tid == 0) {
                unsigned int one = 1u;
                asm volatile("red.release.gpu.global.add.u32 [%0], %1;"
                             :: "l"(barp), "r"(one) : "memory");
                unsigned int want = (unsigned int)(t + 1) * 64u;
                unsigned int vv;
                do {
                    asm volatile("ld.acquire.gpu.global.u32 %0, [%1];"
                                 : "=r"(vv) : "l"(barp));
                } while (vv < want);
            }
            __syncthreads();
        }
    }
}

// ------------------------- launch -------------------------
extern "C" void kernel_launch(void* const* d_in, const int* in_sizes, int n_in,
                              void* d_out, int out_size)
{
    (void)in_sizes; (void)n_in; (void)out_size;
    const float* x = (const float*)d_in[0];

    cudaFuncSetAttribute(mma_gemm, cudaFuncAttributeMaxDynamicSharedMemorySize, MG_SMEM);
    cudaFuncSetAttribute(recur_tc, cudaFuncAttributeMaxDynamicSharedMemorySize, RT_SMEM);

    prep_kernel<<<512, 256>>>(
        (const float*)d_in[1],  (const float*)d_in[5],
        (const float*)d_in[2],  (const float*)d_in[6],
        (const float*)d_in[3],  (const float*)d_in[4],
        (const float*)d_in[7],  (const float*)d_in[11],
        (const float*)d_in[8],  (const float*)d_in[12],
        (const float*)d_in[9],  (const float*)d_in[10]);

    float* bias0; cudaGetSymbolAddress((void**)&bias0, g_bias0);
    float* bias1; cudaGetSymbolAddress((void**)&bias1, g_bias1);
    float* xW;    cudaGetSymbolAddress((void**)&xW,    g_xW);
    __nv_bfloat16 *Ah, *Al, *W0h, *W0l, *W1h, *W1l;
    cudaGetSymbolAddress((void**)&Ah,  g_Ah);
    cudaGetSymbolAddress((void**)&Al,  g_Al);
    cudaGetSymbolAddress((void**)&W0h, g_W0h);
    cudaGetSymbolAddress((void**)&W0l, g_W0l);
    cudaGetSymbolAddress((void**)&W1h, g_W1h);
    cudaGetSymbolAddress((void**)&W1l, g_W1l);

    dim3 mgrid(G / 64, (T * B) / 128);

    // layer 0
    convert_x<<<512, 256>>>(x);
    reset_state<<<(B * H + 255) / 256, 256>>>();
    mma_gemm<<<mgrid, 256, MG_SMEM>>>(Ah, Al, W0h, W0l, bias0, xW, DIN);
    recur_tc<<<NCTA, 512, RT_SMEM>>>((float*)0, 0);

    // layer 1 (g_Ah/g_Al hold layer0's h sequence — no convert needed)
    mma_gemm<<<mgrid, 256, MG_SMEM>>>(Ah, Al, W1h, W1l, bias1, xW, H);
    reset_state<<<(B * H + 255) / 256, 256>>>();
    recur_tc<<<NCTA, 512, RT_SMEM>>>((float*)d_out, 1);
}

// round 12
// speedup vs baseline: 2.1432x; 1.1563x over previous
#include <cuda_runtime.h>
#include <cuda_bf16.h>
#include <cstdint>

// Problem constants
#define B    64
#define T    512
#define DIN  256
#define H    512
#define G    2048   // 4*H

#define NCTA 128

// mma_gemm tile config (proven R8)
#define MG_BUF   24576
#define MG_SMEM  (2 * MG_BUF)

// recur_tc SMEM layout (bytes): Whi @0 | Wlo @32768 | Hhi @65536 | part @98304
#define RT_PART_OFF 98304
#define RT_SMEM     (98304 + 4 * 32 * 34 * 4)   // 115712

typedef unsigned long long u64;

// ------------------------- device scratch -------------------------
__device__ float g_Whh0[G * H];
__device__ float g_Whh1[G * H];
__device__ float g_bias0[G];
__device__ float g_bias1[G];
__device__ float g_xW[(size_t)T * B * G];            // [t*B+b][G]
__device__ unsigned int g_bar2[2][16];
// bf16 hi/lo activations: x (layer0 input) then layer0 h-sequence
__device__ __nv_bfloat16 g_Ah[(size_t)T * B * H];
__device__ __nv_bfloat16 g_Al[(size_t)T * B * H];
// layer1 double-buffered h state (bf16 hi only); buf[0] doubles as t=0 zeros
__device__ __nv_bfloat16 g_h1h[2][B * H];
// masked+split input-projection weights
__device__ __nv_bfloat16 g_W0h[G * DIN], g_W0l[G * DIN];
__device__ __nv_bfloat16 g_W1h[G * H],   g_W1l[G * H];

// ------------------------- helpers -------------------------
__device__ __forceinline__ float sigmf(float x) {
    return 1.0f / (1.0f + __expf(-x));
}
__device__ __forceinline__ uint32_t smem_u32(const void* p) {
    uint32_t a;
    asm("{ .reg .u64 t; cvta.to.shared.u64 t, %1; cvt.u32.u64 %0, t; }" : "=r"(a) : "l"(p));
    return a;
}
__device__ __forceinline__ void ldsm4(uint32_t* r, uint32_t addr) {
    asm volatile("ldmatrix.sync.aligned.m8n8.x4.shared.b16 {%0,%1,%2,%3}, [%4];"
                 : "=r"(r[0]), "=r"(r[1]), "=r"(r[2]), "=r"(r[3]) : "r"(addr));
}
__device__ __forceinline__ void mma16816(float* d, const uint32_t* a, const uint32_t* b) {
    asm volatile(
        "mma.sync.aligned.m16n8k16.row.col.f32.bf16.bf16.f32 "
        "{%0,%1,%2,%3}, {%4,%5,%6,%7}, {%8,%9}, {%0,%1,%2,%3};"
        : "+f"(d[0]), "+f"(d[1]), "+f"(d[2]), "+f"(d[3])
        : "r"(a[0]), "r"(a[1]), "r"(a[2]), "r"(a[3]), "r"(b[0]), "r"(b[1]));
}
__device__ __forceinline__ void st_bf16_cg(__nv_bfloat16* p, __nv_bfloat16 v) {
    unsigned short u = *(unsigned short*)&v;
    asm volatile("st.global.cg.u16 [%0], %1;" :: "l"(p), "h"(u) : "memory");
}

// ------------------------- prep -------------------------
__global__ void prep_kernel(const float* Wih0, const float* mih0,
                            const float* Whh0, const float* mhh0,
                            const float* bih0, const float* bhh0,
                            const float* Wih1, const float* mih1,
                            const float* Whh1, const float* mhh1,
                            const float* bih1, const float* bhh1)
{
    int idx0 = blockIdx.x * blockDim.x + threadIdx.x;
    int stride = gridDim.x * blockDim.x;
    for (int i = idx0; i < G * H; i += stride) g_Whh0[i] = Whh0[i] * mhh0[i];
    for (int i = idx0; i < G * H; i += stride) g_Whh1[i] = Whh1[i] * mhh1[i];
    for (int i = idx0; i < G * DIN; i += stride) {
        float v = Wih0[i] * mih0[i];
        __nv_bfloat16 h = __float2bfloat16(v);
        g_W0h[i] = h;
        g_W0l[i] = __float2bfloat16(v - __bfloat162float(h));
    }
    for (int i = idx0; i < G * H; i += stride) {
        float v = Wih1[i] * mih1[i];
        __nv_bfloat16 h = __float2bfloat16(v);
        g_W1h[i] = h;
        g_W1l[i] = __float2bfloat16(v - __bfloat162float(h));
    }
    for (int i = idx0; i < G; i += stride) {
        g_bias0[i] = bih0[i] + bhh0[i];
        g_bias1[i] = bih1[i] + bhh1[i];
    }
}

__global__ void reset_state() {
    int i = blockIdx.x * blockDim.x + threadIdx.x;
    if (i < B * H) {
        __nv_bfloat16 z = __float2bfloat16(0.0f);
        g_h1h[0][i] = z; g_h1h[1][i] = z;
    }
    if (i < 32) g_bar2[i >> 4][i & 15] = 0u;
}

// convert x [B,T,DIN] -> hi/lo [t*B+b][DIN]
__global__ void convert_x(const float* __restrict__ x) {
    int i = blockIdx.x * blockDim.x + threadIdx.x;
    int n = T * B * DIN;
    for (; i < n; i += gridDim.x * blockDim.x) {
        int m = i / DIN, k = i - m * DIN;
        int b = m & (B - 1), t = m >> 6;
        float v = x[(size_t)(b * T + t) * DIN + k];
        __nv_bfloat16 h = __float2bfloat16(v);
        g_Ah[i] = h;
        g_Al[i] = __float2bfloat16(v - __bfloat162float(h));
    }
}

// ------------------------- warp-MMA projection GEMM (proven R8, 3-term) -------------------------
__global__ void __launch_bounds__(256) mma_gemm(
    const __nv_bfloat16* __restrict__ Ah, const __nv_bfloat16* __restrict__ Al,
    const __nv_bfloat16* __restrict__ Wh, const __nv_bfloat16* __restrict__ Wl,
    const float* __restrict__ bias, float* __restrict__ C, int K)
{
    extern __shared__ char smc[];
    __shared__ float s_bias[64];

    const int tid = threadIdx.x;
    const int w   = tid >> 5;
    const int ln  = tid & 31;
    const int m0  = blockIdx.y << 7;
    const int n0  = blockIdx.x << 6;
    const int mw  = (w >> 1) << 5;
    const int nw  = (w & 1) << 5;

    if (tid < 64) s_bias[tid] = __ldg(&bias[n0 + tid]);

    const uint32_t ub = smem_u32(smc);

    int a_s[2]; size_t a_g[2];
#pragma unroll
    for (int i = 0; i < 2; i++) {
        int u  = tid + 256 * i;
        int ar = u >> 2, ac = u & 3;
        a_s[i] = ar * 64 + ((ac ^ ((ar >> 1) & 3)) << 4);
        a_g[i] = (size_t)(m0 + ar) * K + ac * 8;
    }
    const int wr  = tid >> 2, wc2 = tid & 3;
    const int w_s = wr * 64 + ((wc2 ^ ((wr >> 1) & 3)) << 4);
    const size_t w_g = (size_t)(n0 + wr) * K + wc2 * 8;

    const int arl  = (ln & 7) + ((ln >> 3) & 1) * 8;
    const int akh  = (ln >> 4) & 1;
    const int swzA = (arl >> 1) & 3;
    const int brl  = (ln & 7) + ((ln >> 4) & 1) * 8;
    const int bkh  = (ln >> 3) & 1;
    const int swzB = (brl >> 1) & 3;

    float acc[2][4][4];
#pragma unroll
    for (int mi = 0; mi < 2; mi++)
#pragma unroll
        for (int nj = 0; nj < 4; nj++)
#pragma unroll
            for (int q = 0; q < 4; q++) acc[mi][nj][q] = 0.0f;

    const int NC = K >> 5;

    {
        char* bp = smc;
#pragma unroll
        for (int i = 0; i < 2; i++) {
            uint4 vh = __ldg((const uint4*)(Ah + a_g[i]));
            uint4 vl = __ldg((const uint4*)(Al + a_g[i]));
            *(uint4*)(bp + a_s[i])        = vh;
            *(uint4*)(bp + 8192 + a_s[i]) = vl;
        }
        uint4 wh = __ldg((const uint4*)(Wh + w_g));
        uint4 wl = __ldg((const uint4*)(Wl + w_g));
        *(uint4*)(bp + 16384 + w_s) = wh;
        *(uint4*)(bp + 20480 + w_s) = wl;
    }
    __syncthreads();

    for (int c = 0; c < NC; c++) {
        uint4 rah[2], ral[2], rwh, rwl;
        if (c + 1 < NC) {
            size_t ko = (size_t)(c + 1) * 32;
#pragma unroll
            for (int i = 0; i < 2; i++) {
                rah[i] = __ldg((const uint4*)(Ah + a_g[i] + ko));
                ral[i] = __ldg((const uint4*)(Al + a_g[i] + ko));
            }
            rwh = __ldg((const uint4*)(Wh + w_g + ko));
            rwl = __ldg((const uint4*)(Wl + w_g + ko));
        }

        const uint32_t base = ub + (uint32_t)(c & 1) * MG_BUF;
#pragma unroll
        for (int s = 0; s < 2; s++) {
            uint32_t fah[2][4], fal[2][4], fbh[2][4], fbl[2][4];
#pragma unroll
            for (int mi = 0; mi < 2; mi++) {
                int row = mw + mi * 16 + arl;
                uint32_t off = row * 64 + (((2 * s + akh) ^ swzA) << 4);
                ldsm4(fah[mi], base + off);
                ldsm4(fal[mi], base + 8192 + off);
            }
#pragma unroll
            for (int nj2 = 0; nj2 < 2; nj2++) {
                int row = nw + nj2 * 16 + brl;
                uint32_t off = row * 64 + (((2 * s + bkh) ^ swzB) << 4);
                ldsm4(fbh[nj2], base + 16384 + off);
                ldsm4(fbl[nj2], base + 20480 + off);
            }
#pragma unroll
            for (int mi = 0; mi < 2; mi++)
#pragma unroll
                for (int nj2 = 0; nj2 < 2; nj2++)
#pragma unroll
                    for (int hh = 0; hh < 2; hh++) {
                        float* d = acc[mi][nj2 * 2 + hh];
                        mma16816(d, fah[mi], &fbh[nj2][hh * 2]);
                        mma16816(d, fal[mi], &fbh[nj2][hh * 2]);
                        mma16816(d, fah[mi], &fbl[nj2][hh * 2]);
                    }
        }

        if (c + 1 < NC) {
            char* bp = smc + ((c + 1) & 1) * MG_BUF;
#pragma unroll
            for (int i = 0; i < 2; i++) {
                *(uint4*)(bp + a_s[i])        = rah[i];
                *(uint4*)(bp + 8192 + a_s[i]) = ral[i];
            }
            *(uint4*)(bp + 16384 + w_s) = rwh;
            *(uint4*)(bp + 20480 + w_s) = rwl;
            __syncthreads();
        }
    }

    const int er = ln >> 2;
    const int ec = (ln & 3) * 2;
#pragma unroll
    for (int mi = 0; mi < 2; mi++) {
#pragma unroll
        for (int nj = 0; nj < 4; nj++) {
            int row = m0 + mw + mi * 16 + er;
            int cl  = nw + nj * 8 + ec;
            float b0 = s_bias[cl], b1 = s_bias[cl + 1];
            float2 o0 = make_float2(acc[mi][nj][0] + b0, acc[mi][nj][1] + b1);
            float2 o1 = make_float2(acc[mi][nj][2] + b0, acc[mi][nj][3] + b1);
            *(float2*)&C[(size_t)row * G + n0 + cl]       = o0;
            *(float2*)&C[(size_t)(row + 8) * G + n0 + cl] = o1;
        }
    }
}

// ------------------------- tensor-core recurrence (v4: 2-term, staging FIXED) -------------------------
// 128 CTAs (8 units x 32 batches). W split (hi/lo) in registers; h staged as
// bf16 HI ONLY — full 32x512 tile = 64 uint4 per row, 4 uint4 per thread.
// Layer0 still writes h hi+lo so layer1's projection stays 3-term accurate.
__global__ void __launch_bounds__(512, 1) recur_tc(float* outArg, int layer)
{
    extern __shared__ char smraw[];
    char*  Whi = smraw;
    char*  Wlo = smraw + 32768;
    char*  Hhi = smraw + 65536;
    float* part = (float*)(smraw + RT_PART_OFF);   // [4 kq][32 row][34]

    const float* Whh = layer ? g_Whh1 : g_Whh0;
    const int tid = threadIdx.x;
    const int w   = tid >> 5;
    const int ln  = tid & 31;
    const int mh  = w >> 3;           // m half: rows mh*16..+15
    const int nh  = (w >> 2) & 1;     // n half: batches nh*16..+15
    const int kq  = w & 3;            // K quarter
    const int unit0 = (blockIdx.x >> 1) * 8;
    const int bh    = blockIdx.x & 1;
    const int bb0   = bh * 32;
    unsigned int* barp = &g_bar2[bh][0];

    // ---- convert + stage W_hh into swizzled SMEM (once) ----
    for (int i = tid; i < 32 * 512; i += 512) {
        int r = i >> 9, k = i & 511;
        int u = r >> 2, g = r & 3;
        float v = __ldg(&Whh[(size_t)(g * H + unit0 + u) * H + k]);
        __nv_bfloat16 hi = __float2bfloat16(v);
        __nv_bfloat16 lo = __float2bfloat16(v - __bfloat162float(hi));
        int off = r * 1024 + (((k >> 3) ^ (r & 7)) << 4) + (k & 7) * 2;
        *(__nv_bfloat16*)(Whi + off) = hi;
        *(__nv_bfloat16*)(Wlo + off) = lo;
    }
    __syncthreads();

    // ---- ldmatrix lane constants (proven mapping) ----
    const int arl = (ln & 7) + ((ln >> 3) & 1) * 8;
    const int akh = (ln >> 4) & 1;
    const int brl = (ln & 7) + ((ln >> 4) & 1) * 8;
    const int bkh = (ln >> 3) & 1;
    const int rowA = mh * 16 + arl;
    const int rowB = nh * 16 + brl;
    const uint32_t baseWhi = smem_u32(Whi) + rowA * 1024;
    const uint32_t baseWlo = smem_u32(Wlo) + rowA * 1024;
    const uint32_t baseHhi = smem_u32(Hhi) + rowB * 1024;
    const int aX = rowA & 7;
    const int bX = rowB & 7;

    // ---- hoist W fragments into registers (step-invariant) ----
    uint32_t wfh[8][4], wfl[8][4];
#pragma unroll
    for (int i = 0; i < 8; i++) {
        int c2 = (kq * 8 + i) * 2;
        uint32_t ca = (uint32_t)((c2 + akh) ^ aX) << 4;
        ldsm4(wfh[i], baseWhi + ca);
        ldsm4(wfl[i], baseWlo + ca);
    }

    // epilogue frag coords
    const int er = ln >> 2;
    const int ec = (ln & 3) * 2;

    // staging roles: full 32 rows x 64 uint4 -> 4 uint4/thread (c4 = cj + 16j)
    const int sb = tid >> 4;            // 0..31 batch
    const int cj = tid & 15;            // uint4 phase
    const uint32_t stOff = sb * 1024;

    // activation roles (tid < 256)
    const int ul = tid >> 5;
    const int ab = tid & 31;
    float creg = 0.0f;

    float* outp = layer ? outArg : (float*)0;

    for (int t = 0; t < T; t++) {
        const __nv_bfloat16* hinh;
        if (layer == 0) hinh = (t == 0) ? g_h1h[0] : (g_Ah + (size_t)(t - 1) * B * H);
        else            hinh = g_h1h[t & 1];
        const float* xwt = g_xW + (size_t)t * B * G;

        float xg0 = 0.f, xg1 = 0.f, xg2 = 0.f, xg3 = 0.f;
        if (tid < 256) {
            xg0 = __ldg(&xwt[(bb0 + ab) * G + 0 * H + unit0 + ul]);
            xg1 = __ldg(&xwt[(bb0 + ab) * G + 1 * H + unit0 + ul]);
            xg2 = __ldg(&xwt[(bb0 + ab) * G + 2 * H + unit0 + ul]);
            xg3 = __ldg(&xwt[(bb0 + ab) * G + 3 * H + unit0 + ul]);
        }

        // ---- stage h hi (32 b x 512 = 64 uint4/row), swizzled, one wave ----
        {
            const uint4* gh = (const uint4*)(hinh + (size_t)(bb0 + sb) * H);
            uint4 v[4];
#pragma unroll
            for (int j = 0; j < 4; j++)
                v[j] = __ldcg(gh + cj + 16 * j);
#pragma unroll
            for (int j = 0; j < 4; j++) {
                int c4 = cj + 16 * j;
                *(uint4*)(Hhi + stOff + ((c4 ^ (sb & 7)) << 4)) = v[j];
            }
        }
        __syncthreads();

        // ---- MMA: 2-term (Wh*hh + Wl*hh), h frags from SMEM ----
        float d0[4] = {0, 0, 0, 0}, d1[4] = {0, 0, 0, 0};
#pragma unroll
        for (int i = 0; i < 8; i++) {
            int c2 = (kq * 8 + i) * 2;
            uint32_t fbh[4];
            uint32_t cb = (uint32_t)((c2 + bkh) ^ bX) << 4;
            ldsm4(fbh, baseHhi + cb);
            mma16816(d0, wfh[i], &fbh[0]);
            mma16816(d1, wfh[i], &fbh[2]);
            mma16816(d0, wfl[i], &fbh[0]);
            mma16816(d1, wfl[i], &fbh[2]);
        }

        // ---- write partials: part[kq][row][batch] ----
        {
            float* pb = part + kq * (32 * 34);
            int r0 = mh * 16 + er;
            int c0 = nh * 16 + ec;
            *(float2*)&pb[r0 * 34 + c0]           = make_float2(d0[0], d0[1]);
            *(float2*)&pb[(r0 + 8) * 34 + c0]     = make_float2(d0[2], d0[3]);
            *(float2*)&pb[r0 * 34 + c0 + 8]       = make_float2(d1[0], d1[1]);
            *(float2*)&pb[(r0 + 8) * 34 + c0 + 8] = make_float2(d1[2], d1[3]);
        }
        __syncthreads();

        // ---- activation: thread = (unit ul, batch ab), tid < 256 ----
        if (tid < 256) {
            float gate[4];
#pragma unroll
            for (int g = 0; g < 4; g++) {
                int r = ul * 4 + g;
                gate[g] = part[0 * 32 * 34 + r * 34 + ab]
                        + part[1 * 32 * 34 + r * 34 + ab]
                        + part[2 * 32 * 34 + r * 34 + ab]
                        + part[3 * 32 * 34 + r * 34 + ab];
            }
            float gi = gate[0] + xg0, gf = gate[1] + xg1;
            float gg = gate[2] + xg2, go = gate[3] + xg3;
            creg = sigmf(gf) * creg + sigmf(gi) * __tanhf(gg);
            float hv = sigmf(go) * __tanhf(creg);

            __nv_bfloat16 hhi = __float2bfloat16(hv);
            if (layer == 0) {
                // keep hi+lo so layer1's input projection stays 3-term accurate
                __nv_bfloat16 hlo = __float2bfloat16(hv - __bfloat162float(hhi));
                size_t o = (size_t)(t * B + bb0 + ab) * H + unit0 + ul;
                st_bf16_cg(&g_Ah[o], hhi);
                st_bf16_cg(&g_Al[o], hlo);
            } else {
                size_t o = (size_t)(bb0 + ab) * H + unit0 + ul;
                st_bf16_cg(&g_h1h[(t + 1) & 1][o], hhi);
                if (t == T - 1) outp[o] = hv;
            }
        }

        // ---- per-half grid barrier (64 CTAs) ----
        if (t + 1 < T) {
            __syncthreads();
            if (tid == 0) {
                unsigned int one = 1u;
                asm volatile("red.release.gpu.global.add.u32 [%0], %1;"
                             :: "l"(barp), "r"(one) : "memory");
                unsigned int want = (unsigned int)(t + 1) * 64u;
                unsigned int vv;
                do {
                    asm volatile("ld.acquire.gpu.global.u32 %0, [%1];"
                                 : "=r"(vv) : "l"(barp));
                } while (vv < want);
            }
            __syncthreads();
        }
    }
}

// ------------------------- launch -------------------------
extern "C" void kernel_launch(void* const* d_in, const int* in_sizes, int n_in,
                              void* d_out, int out_size)
{
    (void)in_sizes; (void)n_in; (void)out_size;
    const float* x = (const float*)d_in[0];

    cudaFuncSetAttribute(mma_gemm, cudaFuncAttributeMaxDynamicSharedMemorySize, MG_SMEM);
    cudaFuncSetAttribute(recur_tc, cudaFuncAttributeMaxDynamicSharedMemorySize, RT_SMEM);

    prep_kernel<<<512, 256>>>(
        (const float*)d_in[1],  (const float*)d_in[5],
        (const float*)d_in[2],  (const float*)d_in[6],
        (const float*)d_in[3],  (const float*)d_in[4],
        (const float*)d_in[7],  (const float*)d_in[11],
        (const float*)d_in[8],  (const float*)d_in[12],
        (const float*)d_in[9],  (const float*)d_in[10]);

    float* bias0; cudaGetSymbolAddress((void**)&bias0, g_bias0);
    float* bias1; cudaGetSymbolAddress((void**)&bias1, g_bias1);
    float* xW;    cudaGetSymbolAddress((void**)&xW,    g_xW);
    __nv_bfloat16 *Ah, *Al, *W0h, *W0l, *W1h, *W1l;
    cudaGetSymbolAddress((void**)&Ah,  g_Ah);
    cudaGetSymbolAddress((void**)&Al,  g_Al);
    cudaGetSymbolAddress((void**)&W0h, g_W0h);
    cudaGetSymbolAddress((void**)&W0l, g_W0l);
    cudaGetSymbolAddress((void**)&W1h, g_W1h);
    cudaGetSymbolAddress((void**)&W1l, g_W1l);

    dim3 mgrid(G / 64, (T * B) / 128);

    // layer 0
    convert_x<<<512, 256>>>(x);
    reset_state<<<(B * H + 255) / 256, 256>>>();
    mma_gemm<<<mgrid, 256, MG_SMEM>>>(Ah, Al, W0h, W0l, bias0, xW, DIN);
    recur_tc<<<NCTA, 512, RT_SMEM>>>((float*)0, 0);

    // layer 1 (g_Ah/g_Al hold layer0's h sequence — no convert needed)
    mma_gemm<<<mgrid, 256, MG_SMEM>>>(Ah, Al, W1h, W1l, bias1, xW, H);
    reset_state<<<(B * H + 255) / 256, 256>>>();
    recur_tc<<<NCTA, 512, RT_SMEM>>>((float*)d_out, 1);
}